// round 12
// baseline (speedup 1.0000x reference)
#include <cuda_runtime.h>
#include <math.h>
#include <cstdint>

#define THREADS 128

typedef unsigned long long u64;
typedef unsigned int u32;

// ---------------- f32x2 helpers ----------------
__device__ __forceinline__ u64 ffma2(u64 a, u64 b, u64 c) {
    u64 d; asm("fma.rn.f32x2 %0, %1, %2, %3;" : "=l"(d) : "l"(a), "l"(b), "l"(c)); return d;
}
__device__ __forceinline__ u64 mul2(u64 a, u64 b) {
    u64 d; asm("mul.rn.f32x2 %0, %1, %2;" : "=l"(d) : "l"(a), "l"(b)); return d;
}
__device__ __forceinline__ u64 dup2(float x) {
    u64 d; unsigned u = __float_as_uint(x);
    asm("mov.b64 %0, {%1, %2};" : "=l"(d) : "r"(u), "r"(u)); return d;
}
__device__ __forceinline__ u64 pack2(float a, float b) {
    u64 d; asm("mov.b64 %0, {%1, %2};" : "=l"(d) : "r"(__float_as_uint(a)), "r"(__float_as_uint(b))); return d;
}
__device__ __forceinline__ void unpack2(u64 v, float &lo, float &hi) {
    unsigned a, b; asm("mov.b64 {%0, %1}, %2;" : "=r"(a), "=r"(b) : "l"(v));
    lo = __uint_as_float(a); hi = __uint_as_float(b);
}
__device__ __forceinline__ u64 packu(u32 lo, u32 hi) {
    u64 d; asm("mov.b64 %0, {%1, %2};" : "=l"(d) : "r"(lo), "r"(hi)); return d;
}
__device__ __forceinline__ u32 f2tf32(float f) {
    u32 r; asm("cvt.rna.tf32.f32 %0, %1;" : "=r"(r) : "f"(f)); return r;
}

// mma.sync m16n8k8 tf32 (portable sm_80+ path; runs on tensor pipe)
__device__ __forceinline__ void mma8r(float* acc, u32 a0, u32 a1, u32 a2, u32 a3, u64 b) {
    u32 b0 = (u32)b, b1 = (u32)(b >> 32);
    asm volatile("mma.sync.aligned.m16n8k8.row.col.f32.tf32.tf32.f32 "
                 "{%0,%1,%2,%3}, {%4,%5,%6,%7}, {%8,%9}, {%0,%1,%2,%3};"
                 : "+f"(acc[0]), "+f"(acc[1]), "+f"(acc[2]), "+f"(acc[3])
                 : "r"(a0), "r"(a1), "r"(a2), "r"(a3), "r"(b0), "r"(b1));
}

__device__ __forceinline__ float qredf(float v) {
    v += __shfl_xor_sync(0xffffffffu, v, 1);
    v += __shfl_xor_sync(0xffffffffu, v, 2);
    return v;
}

__device__ __forceinline__ float sel4(int t, float a, float b, float cc, float dd) {
    return t == 0 ? a : (t == 1 ? b : (t == 2 ? cc : dd));
}

// ---------------- smem layout (bytes) — fits 3 CTAs/SM ----------------
#define SM_QS    0        /* float4[128]                       2048 */
#define SM_MP2   2048     /* ulonglong2[128] (H0,H1)           2048 */
#define SM_BQ    4096     /* u64[8kk][4n][4tq]                 1024 */
#define SM_BEXTL 5120     /* u32[256n][4tq]                    4096 */
#define SM_BEXTB 9216     /* u32[256n] bias plane              1024 */
#define SM_AB1   10240    /* 32768: A tile, then BP1 (stage-y) */
#define SM_BP0   43008    /* ulonglong2[4kkp][128n][4tq]       32768 */
#define SMEM_BYTES 75776

#define LK_A 0.84852813742385703f  /* 0.6*sqrt(2) */
#define LK_B 0.56568542494923801f  /* 0.4*sqrt(2) */

__global__ __launch_bounds__(THREADS, 3)
void coupling_mma_kernel(const float* __restrict__ coords,
                         const float* __restrict__ c,
                         const float* __restrict__ Wx1, const float* __restrict__ bx1,
                         const float* __restrict__ Wx2, const float* __restrict__ bx2,
                         const float* __restrict__ Wy1, const float* __restrict__ by1,
                         const float* __restrict__ Wy2, const float* __restrict__ by2,
                         float* __restrict__ out, long M)
{
    extern __shared__ char smem[];
    const int tid  = threadIdx.x;
    const int lane = tid & 31;
    const int warp = tid >> 5;
    const int g    = lane >> 2;     // 0..7
    const int tq   = lane & 3;      // 0..3
    const long base = (long)blockIdx.x * 128;

    const float s1 = 1.0f / sqrtf(68.0f);
    const float s2 = 1.0f / sqrtf(192.0f);

    float4* QS = (float4*)(smem + SM_QS);
    ulonglong2* MP2 = (ulonglong2*)(smem + SM_MP2);
    u64*  BQ    = (u64*)(smem + SM_BQ);
    u32*  BEXTL = (u32*)(smem + SM_BEXTL);
    u32*  BEXTB = (u32*)(smem + SM_BEXTB);
    u32*  AS    = (u32*)(smem + SM_AB1);
    ulonglong2* BP1V = (ulonglong2*)(smem + SM_AB1);
    ulonglong2* BP0V = (ulonglong2*)(smem + SM_BP0);

    // ---------- staging ----------
    // A: c[128 x 64] -> tf32 bits, layout row*64 + (k ^ ((row&7)<<2))
    #pragma unroll
    for (int i = 0; i < 16; i++) {
        int idx = tid + i * THREADS;          // float4 index
        int row = idx >> 4;
        int k4  = (idx & 15) << 2;
        long gr = base + row;
        float4 v = make_float4(0.f, 0.f, 0.f, 0.f);
        if (gr < M) v = *(const float4*)(c + gr * 64 + k4);
        uint4 tv = { f2tf32(v.x), f2tf32(v.y), f2tf32(v.z), f2tf32(v.w) };
        *(uint4*)(AS + row * 64 + (k4 ^ ((row & 7) << 2))) = tv;
    }
    // BP0 [kkp][128][4] ulonglong2: {pair(kk=2kkp), pair(kk=2kkp+1)} for column t
    // element index = kkp*512 + n*4 + t == idx (identity)
    #pragma unroll
    for (int i = 0; i < 16; i++) {
        int idx = tid + i * THREADS;          // 0..2047
        int t   = idx & 3;
        int n   = (idx >> 2) & 127;
        int kkp = idx >> 9;
        int k0 = kkp * 16 + t;
        int k1 = k0 + 8;
        const float* wr = Wx1 + n * 68 + 4;
        ulonglong2 v;
        v.x = packu(f2tf32(wr[k0] * s1), f2tf32(wr[k0 + 4] * s1));
        v.y = packu(f2tf32(wr[k1] * s1), f2tf32(wr[k1 + 4] * s1));
        BP0V[idx] = v;
    }
    // BEXTL [n][tq] = W1s[tq][n] (lo plane);  BEXTB [n] = b1[n] (bias plane)
    #pragma unroll
    for (int i = 0; i < 8; i++) {
        int idx = tid + i * THREADS;          // 0..1023
        int n = idx >> 2;
        int t = idx & 3;
        const float* Wg = (n < 128) ? Wx1 : Wy1;
        BEXTL[idx] = f2tf32(Wg[(n & 127) * 68 + t] * s1);
    }
    #pragma unroll
    for (int i = 0; i < 2; i++) {
        int n = tid + i * THREADS;            // 0..255
        const float* b1g = (n < 128) ? bx1 : by1;
        BEXTB[n] = f2tf32(b1g[n & 127]);
    }
    // BQ [kk][4][4]: q-GEMM weights. col n: 0=qx0,1=qx1,2=qy0,3=qy1
    if (tid < 128) {
        int t  = tid & 3;
        int n  = (tid >> 2) & 3;
        int kk = tid >> 4;
        const float* Wsrc = (n >> 1) ? Wy2 : Wx2;
        int ob = (n & 1) * 192 + 128;
        u32 lo = f2tf32(Wsrc[ob + kk * 8 + t] * s2);
        u32 hi = f2tf32(Wsrc[ob + kk * 8 + t + 4] * s2);
        BQ[tid] = packu(lo, hi);
    }
    // MP2: jp -> (H0, H1)
    {
        int jp = tid;
        int j0 = 2 * jp;
        int st = j0 >> 7;
        int jj0 = j0 & 127, jj1 = jj0 + 1;
        const float* W2g = st ? Wy2 : Wx2;
        ulonglong2 p;
        p.x = pack2(W2g[jj0] * s2, W2g[jj1] * s2);
        p.y = pack2(W2g[192 + jj0] * s2, W2g[192 + jj1] * s2);
        MP2[jp] = p;
    }
    __syncthreads();

    // ---------- A fragments (cached; A smem dies after this) ----------
    u32 afr[2][8][4];
    {
        const int swz = g << 2;   // rows used always have row&7 == g
        #pragma unroll
        for (int mt = 0; mt < 2; mt++) {
            int r0 = warp * 32 + mt * 16 + g;
            #pragma unroll
            for (int kk = 0; kk < 8; kk++) {
                int k0 = kk * 8 + tq;
                afr[mt][kk][0] = AS[r0 * 64 + (k0 ^ swz)];
                afr[mt][kk][1] = AS[(r0 + 8) * 64 + (k0 ^ swz)];
                afr[mt][kk][2] = AS[r0 * 64 + ((k0 + 4) ^ swz)];
                afr[mt][kk][3] = AS[(r0 + 8) * 64 + ((k0 + 4) ^ swz)];
            }
        }
    }

    // ---------- q-GEMM: q[rows, 4] = c @ W2c^T (tensor core) ----------
    {
        float aq[2][4];
        #pragma unroll
        for (int mt = 0; mt < 2; mt++)
            #pragma unroll
            for (int q = 0; q < 4; q++) aq[mt][q] = 0.0f;
        const u64* bq = BQ + (g & 3) * 4 + tq;   // lanes g>=4 alias cols 0-3 (unused outputs)
        #pragma unroll
        for (int kk = 0; kk < 8; kk++) {
            u64 b = bq[kk * 16];
            mma8r(aq[0], afr[0][kk][0], afr[0][kk][1], afr[0][kk][2], afr[0][kk][3], b);
            mma8r(aq[1], afr[1][kk][0], afr[1][kk][1], afr[1][kk][2], afr[1][kk][3], b);
        }
        // C frag: (rows r0|r0+8, cols 2tq,2tq+1). tq=0 -> (qx0,qx1), tq=1 -> (qy0,qy1).
        if (tq < 2) {
            float b0 = tq ? by2[0] : bx2[0];
            float b1 = tq ? by2[1] : bx2[1];
            #pragma unroll
            for (int mt = 0; mt < 2; mt++) {
                int r0 = warp * 32 + mt * 16 + g;
                *(u64*)((float*)&QS[r0]     + tq * 2) = pack2(aq[mt][0] + b0, aq[mt][1] + b1);
                *(u64*)((float*)&QS[r0 + 8] + tq * 2) = pack2(aq[mt][2] + b0, aq[mt][3] + b1);
            }
        }
    }
    __syncthreads();   // all afr loaded; A region may now be overwritten

    // ---------- restage: BP1 [kkp][128][4] = stage-y weights (Wy1) over A ----------
    // LDG latency overlaps the stage-0 mainloop issue below (no wait until st=1).
    #pragma unroll
    for (int i = 0; i < 16; i++) {
        int idx = tid + i * THREADS;          // 0..2047
        int t   = idx & 3;
        int n   = (idx >> 2) & 127;
        int kkp = idx >> 9;
        int k0 = kkp * 16 + t;
        int k1 = k0 + 8;
        const float* wr = Wy1 + n * 68 + 4;
        ulonglong2 v;
        v.x = packu(f2tf32(wr[k0] * s1), f2tf32(wr[k0 + 4] * s1));
        v.y = packu(f2tf32(wr[k1] * s1), f2tf32(wr[k1 + 4] * s1));
        BP1V[idx] = v;
    }

    // rows owned by this thread (quad-redundant)
    int R[4];
    #pragma unroll
    for (int ri = 0; ri < 4; ri++) R[ri] = warp * 32 + ri * 8 + g;

    float cin[4], cup[4], lsum[4];
    #pragma unroll
    for (int ri = 0; ri < 4; ri++) {
        long rr = base + R[ri];
        float2 xy = make_float2(0.f, 0.f);
        if (rr < M) xy = ((const float2*)coords)[rr];
        cin[ri] = xy.x; cup[ri] = xy.y; lsum[ri] = 0.0f;
    }

    const u64 lkA = dup2(LK_A), lkB = dup2(LK_B);
    const u64 ABSM = 0x7FFFFFFF7FFFFFFFull;
    const u32 eone = (tq == 0) ? 0x3F800000u : 0u;  // feat[k=4] = 1 (bias column)
    const ulonglong2* bp0t = BP0V + g * 4 + tq;
    const ulonglong2* bp1t = BP1V + g * 4 + tq;
    const u32* belt = BEXTL + g * 4 + tq;
    const u32* bebt = BEXTB + g;

    for (int st = 0; st < 2; st++) {
        if (st == 1) __syncthreads();   // BP1 stores visible before stage-1 reads

        const ulonglong2* bpt = st ? bp1t : bp0t;
        const int noff = st * 128;      // BEXT plane offset

        // per-row sin features (registers; quad-uniform inputs)
        float4 fs[4];
        #pragma unroll
        for (int ri = 0; ri < 4; ri++) {
            float a = cin[ri] * 0.1f, sa, ca;
            sincosf(a, &sa, &ca);
            fs[ri] = make_float4(sa, 2.0f * sa * ca, ca, 1.0f - 2.0f * sa * sa);
        }
        u32 e0[2], e1[2];
        #pragma unroll
        for (int mt = 0; mt < 2; mt++) {
            e0[mt] = f2tf32(sel4(tq, fs[2 * mt].x,     fs[2 * mt].y,     fs[2 * mt].z,     fs[2 * mt].w));
            e1[mt] = f2tf32(sel4(tq, fs[2 * mt + 1].x, fs[2 * mt + 1].y, fs[2 * mt + 1].z, fs[2 * mt + 1].w));
        }

        u64 po0[4], po1[4];
        #pragma unroll
        for (int ri = 0; ri < 4; ri++) { po0[ri] = pack2(0.f, 0.f); po1[ri] = po0[ri]; }

        for (int chunk = 0; chunk < 4; chunk++) {
            int nbase = chunk * 4;                // n-tile within stage (0..15)
            float acc[2][4][4];
            #pragma unroll
            for (int mt = 0; mt < 2; mt++)
                #pragma unroll
                for (int nt = 0; nt < 4; nt++)
                    #pragma unroll
                    for (int q = 0; q < 4; q++) acc[mt][nt][q] = 0.0f;

            // K-extension step (sin features + bias) starts the acc chains
            #pragma unroll
            for (int nt = 0; nt < 4; nt++) {
                int nb = (nbase + nt) * 8;
                u32 lo = belt[(noff + nb) * 4];
                u32 hi = (tq == 0) ? bebt[noff + nb] : 0u;
                u64 be = packu(lo, hi);
                mma8r(acc[0][nt], e0[0], e1[0], eone, eone, be);
                mma8r(acc[1][nt], e0[1], e1[1], eone, eone, be);
            }

            // kk-pair mainloop: 4 LDS.128 feed 16 mma per kkp
            #pragma unroll
            for (int kkp = 0; kkp < 4; kkp++) {
                ulonglong2 bfr[4];
                #pragma unroll
                for (int nt = 0; nt < 4; nt++)
                    bfr[nt] = bpt[kkp * 512 + (nbase + nt) * 32];
                // even kk wave: 8 independent acc chains
                #pragma unroll
                for (int nt = 0; nt < 4; nt++) {
                    mma8r(acc[0][nt], afr[0][2*kkp][0], afr[0][2*kkp][1], afr[0][2*kkp][2], afr[0][2*kkp][3], bfr[nt].x);
                    mma8r(acc[1][nt], afr[1][2*kkp][0], afr[1][2*kkp][1], afr[1][2*kkp][2], afr[1][2*kkp][3], bfr[nt].x);
                }
                // odd kk wave
                #pragma unroll
                for (int nt = 0; nt < 4; nt++) {
                    mma8r(acc[0][nt], afr[0][2*kkp+1][0], afr[0][2*kkp+1][1], afr[0][2*kkp+1][2], afr[0][2*kkp+1][3], bfr[nt].y);
                    mma8r(acc[1][nt], afr[1][2*kkp+1][0], afr[1][2*kkp+1][1], afr[1][2*kkp+1][2], afr[1][2*kkp+1][3], bfr[nt].y);
                }
            }

            // epilogue: leaky + dot into o partials (bias+sin already in acc)
            #pragma unroll
            for (int nt = 0; nt < 4; nt++) {
                int jp = st * 64 + (nbase + nt) * 4 + tq;
                ulonglong2 P = MP2[jp];
                u64 H0 = P.x, H1 = P.y;
                #pragma unroll
                for (int mt = 0; mt < 2; mt++) {
                    #pragma unroll
                    for (int h = 0; h < 2; h++) {
                        int ri = mt * 2 + h;
                        u64 v = pack2(acc[mt][nt][2 * h + 0], acc[mt][nt][2 * h + 1]);
                        u64 av = v & ABSM;
                        u64 hh = ffma2(lkA, v, mul2(lkB, av));
                        po0[ri] = ffma2(hh, H0, po0[ri]);
                        po1[ri] = ffma2(hh, H1, po1[ri]);
                    }
                }
            }
        }

        // reduce + coordinate update
        #pragma unroll
        for (int ri = 0; ri < 4; ri++) {
            float a0, a1, b0, b1;
            unpack2(po0[ri], a0, a1);
            unpack2(po1[ri], b0, b1);
            float o0 = qredf(a0 + a1);
            float o1 = qredf(b0 + b1);
            float4 qv = QS[R[ri]];
            o0 += st ? qv.z : qv.x;
            o1 += st ? qv.w : qv.y;
            float ls = fminf(fmaxf(o0, -5.0f), 5.0f);
            float up_new = cup[ri] * __expf(ls) + o1;
            lsum[ri] += ls;
            cup[ri] = cin[ri];
            cin[ri] = up_new;
        }
    }

    // after stage 1: cin = x_final, cup = y_final. tq==0 lanes store directly.
    if (tq == 0) {
        #pragma unroll
        for (int ri = 0; ri < 4; ri++) {
            long rr = base + R[ri];
            if (rr < M) {
                ((float2*)out)[rr] = make_float2(cin[ri], cup[ri]);
                out[2 * M + rr] = lsum[ri];
            }
        }
    }
}

extern "C" void kernel_launch(void* const* d_in, const int* in_sizes, int n_in,
                              void* d_out, int out_size) {
    const float* coords = (const float*)d_in[0];
    const float* c      = (const float*)d_in[1];
    const float* Wx1    = (const float*)d_in[2];
    const float* bx1    = (const float*)d_in[3];
    const float* Wx2    = (const float*)d_in[4];
    const float* bx2    = (const float*)d_in[5];
    const float* Wy1    = (const float*)d_in[6];
    const float* by1    = (const float*)d_in[7];
    const float* Wy2    = (const float*)d_in[8];
    const float* by2    = (const float*)d_in[9];
    float* out = (float*)d_out;

    long M = (long)in_sizes[1] / 64;
    int grid = (int)((M + 127) / 128);

    cudaFuncSetAttribute(coupling_mma_kernel,
                         cudaFuncAttributeMaxDynamicSharedMemorySize, SMEM_BYTES);
    coupling_mma_kernel<<<grid, THREADS, SMEM_BYTES>>>(coords, c,
                                                       Wx1, bx1, Wx2, bx2,
                                                       Wy1, by1, Wy2, by2,
                                                       out, M);
}

// round 13
// speedup vs baseline: 1.1203x; 1.1203x over previous
#include <cuda_runtime.h>
#include <math.h>
#include <cstdint>

#define THREADS 128

typedef unsigned long long u64;
typedef unsigned int u32;

// ---------------- f32x2 helpers ----------------
__device__ __forceinline__ u64 ffma2(u64 a, u64 b, u64 c) {
    u64 d; asm("fma.rn.f32x2 %0, %1, %2, %3;" : "=l"(d) : "l"(a), "l"(b), "l"(c)); return d;
}
__device__ __forceinline__ u64 mul2(u64 a, u64 b) {
    u64 d; asm("mul.rn.f32x2 %0, %1, %2;" : "=l"(d) : "l"(a), "l"(b)); return d;
}
__device__ __forceinline__ u64 dup2(float x) {
    u64 d; unsigned u = __float_as_uint(x);
    asm("mov.b64 %0, {%1, %2};" : "=l"(d) : "r"(u), "r"(u)); return d;
}
__device__ __forceinline__ u64 pack2(float a, float b) {
    u64 d; asm("mov.b64 %0, {%1, %2};" : "=l"(d) : "r"(__float_as_uint(a)), "r"(__float_as_uint(b))); return d;
}
__device__ __forceinline__ void unpack2(u64 v, float &lo, float &hi) {
    unsigned a, b; asm("mov.b64 {%0, %1}, %2;" : "=r"(a), "=r"(b) : "l"(v));
    lo = __uint_as_float(a); hi = __uint_as_float(b);
}
__device__ __forceinline__ u64 packu(u32 lo, u32 hi) {
    u64 d; asm("mov.b64 %0, {%1, %2};" : "=l"(d) : "r"(lo), "r"(hi)); return d;
}
// pack two f32 -> f16x2 (lo in bits[15:0], hi in bits[31:16])
__device__ __forceinline__ u32 f16x2p(float lo, float hi) {
    u32 r; asm("cvt.rn.f16x2.f32 %0, %1, %2;" : "=r"(r) : "f"(hi), "f"(lo)); return r;
}

// mma.sync m16n8k16 fp16 -> f32 accum (portable sm_80+ path; tensor pipe, 2x tf32 rate)
__device__ __forceinline__ void mma16(float* acc, u32 a0, u32 a1, u32 a2, u32 a3, u32 b0, u32 b1) {
    asm volatile("mma.sync.aligned.m16n8k16.row.col.f32.f16.f16.f32 "
                 "{%0,%1,%2,%3}, {%4,%5,%6,%7}, {%8,%9}, {%0,%1,%2,%3};"
                 : "+f"(acc[0]), "+f"(acc[1]), "+f"(acc[2]), "+f"(acc[3])
                 : "r"(a0), "r"(a1), "r"(a2), "r"(a3), "r"(b0), "r"(b1));
}

__device__ __forceinline__ float qredf(float v) {
    v += __shfl_xor_sync(0xffffffffu, v, 1);
    v += __shfl_xor_sync(0xffffffffu, v, 2);
    return v;
}

// ---------------- smem layout (bytes) — fits 3 CTAs/SM, both stages resident ----------------
#define SM_QS    0        /* float4[128]                         2048 */
#define SM_MP2   2048     /* ulonglong2[128] (H0,H1)             2048 */
#define SM_BQ    4096     /* u64[4kb][4n][4tq]                   512  */
#define SM_BEXT  4608     /* u32[256n][4tq]  f16x2 pairs         4096 */
#define SM_A     8704     /* u32[128row][32] f16x2, xor-swz      16384 */
#define SM_BP    25088    /* u64[2st][4kb][128n][4tq] f16 pairs  32768 */
#define SMEM_BYTES 57856

#define LK_A 0.84852813742385703f  /* 0.6*sqrt(2) */
#define LK_B 0.56568542494923801f  /* 0.4*sqrt(2) */

__global__ __launch_bounds__(THREADS, 3)
void coupling_mma_kernel(const float* __restrict__ coords,
                         const float* __restrict__ c,
                         const float* __restrict__ Wx1, const float* __restrict__ bx1,
                         const float* __restrict__ Wx2, const float* __restrict__ bx2,
                         const float* __restrict__ Wy1, const float* __restrict__ by1,
                         const float* __restrict__ Wy2, const float* __restrict__ by2,
                         float* __restrict__ out, long M)
{
    extern __shared__ char smem[];
    const int tid  = threadIdx.x;
    const int lane = tid & 31;
    const int warp = tid >> 5;
    const int g    = lane >> 2;     // 0..7
    const int tq   = lane & 3;      // 0..3
    const long base = (long)blockIdx.x * 128;

    const float s1 = 1.0f / sqrtf(68.0f);
    const float s2 = 1.0f / sqrtf(192.0f);

    float4* QS = (float4*)(smem + SM_QS);
    ulonglong2* MP2 = (ulonglong2*)(smem + SM_MP2);
    u64*  BQ   = (u64*)(smem + SM_BQ);
    u32*  BEXT = (u32*)(smem + SM_BEXT);
    u32*  AS   = (u32*)(smem + SM_A);
    u64*  BP   = (u64*)(smem + SM_BP);

    // ---------- staging ----------
    // A: c[128 x 64] -> f16 pairs, u32 idx = row*32 + (p ^ ((row&7)<<2)), p = k/2
    #pragma unroll
    for (int i = 0; i < 8; i++) {
        int idx = tid + i * THREADS;          // 0..1023
        int row = idx >> 3;
        int k8  = idx & 7;                    // group of 8 floats
        long gr = base + row;
        float4 v0 = make_float4(0.f, 0.f, 0.f, 0.f), v1 = v0;
        if (gr < M) {
            v0 = *(const float4*)(c + gr * 64 + k8 * 8);
            v1 = *(const float4*)(c + gr * 64 + k8 * 8 + 4);
        }
        uint4 tv = { f16x2p(v0.x, v0.y), f16x2p(v0.z, v0.w),
                     f16x2p(v1.x, v1.y), f16x2p(v1.z, v1.w) };
        *(uint4*)(AS + row * 32 + ((k8 * 4) ^ ((row & 7) << 2))) = tv;
    }
    // BP [st][kb][128n][4tq]: u64 {f16x2(w[k0],w[k0+1]), f16x2(w[k0+8],w[k0+9])},
    // k0 = kb*16 + 2tq, weights prescaled by s1. Both stages staged up-front.
    #pragma unroll
    for (int i = 0; i < 32; i++) {
        int idx = tid + i * THREADS;          // 0..4095
        int t   = idx & 3;
        int n   = (idx >> 2) & 127;
        int kb  = (idx >> 9) & 3;
        int st  = idx >> 11;
        const float* wr = (st ? Wy1 : Wx1) + n * 68 + 4;
        int k0 = kb * 16 + 2 * t;
        float2 wa = *(const float2*)(wr + k0);
        float2 wb = *(const float2*)(wr + k0 + 8);
        BP[idx] = packu(f16x2p(wa.x * s1, wa.y * s1), f16x2p(wb.x * s1, wb.y * s1));
    }
    // BEXT [n][tq]: f16x2 pair (bext[2tq], bext[2tq+1]) with
    // bext = [W1s0,W1s1,W1s2,W1s3 (xs1), b1, 0, 0, 0]
    #pragma unroll
    for (int i = 0; i < 8; i++) {
        int idx = tid + i * THREADS;          // 0..1023
        int n = idx >> 2;
        int t = idx & 3;
        const float* Wg  = (n < 128) ? Wx1 : Wy1;
        const float* b1g = (n < 128) ? bx1 : by1;
        int row = n & 127;
        float lo, hi;
        if (t == 0)      { lo = Wg[row * 68 + 0] * s1; hi = Wg[row * 68 + 1] * s1; }
        else if (t == 1) { lo = Wg[row * 68 + 2] * s1; hi = Wg[row * 68 + 3] * s1; }
        else if (t == 2) { lo = b1g[row];              hi = 0.0f; }
        else             { lo = 0.0f;                  hi = 0.0f; }
        BEXT[idx] = f16x2p(lo, hi);
    }
    // BQ [kb][4n][4tq]: q-GEMM weights (scale s2). col n: 0=qx0,1=qx1,2=qy0,3=qy1
    if (tid < 64) {
        int t  = tid & 3;
        int n  = (tid >> 2) & 3;
        int kb = tid >> 4;
        const float* Wsrc = (n >> 1) ? Wy2 : Wx2;
        const float* wr = Wsrc + (n & 1) * 192 + 128;
        int k0 = kb * 16 + 2 * t;
        BQ[tid] = packu(f16x2p(wr[k0] * s2,     wr[k0 + 1] * s2),
                        f16x2p(wr[k0 + 8] * s2, wr[k0 + 9] * s2));
    }
    // MP2: jp -> (H0, H1) f32 pairs
    {
        int jp = tid;
        int j0 = 2 * jp;
        int st = j0 >> 7;
        int jj0 = j0 & 127, jj1 = jj0 + 1;
        const float* W2g = st ? Wy2 : Wx2;
        ulonglong2 p;
        p.x = pack2(W2g[jj0] * s2, W2g[jj1] * s2);
        p.y = pack2(W2g[192 + jj0] * s2, W2g[192 + jj1] * s2);
        MP2[jp] = p;
    }
    __syncthreads();

    // ---------- A fragments (m16n8k16): afr[mt][kb] = {a0,a1,a2,a3} ----------
    u32 afr[2][4][4];
    {
        const int swz = g << 2;
        #pragma unroll
        for (int mt = 0; mt < 2; mt++) {
            int r0 = warp * 32 + mt * 16 + g;
            #pragma unroll
            for (int kb = 0; kb < 4; kb++) {
                int p0 = kb * 8 + tq;
                afr[mt][kb][0] = AS[r0 * 32 + (p0 ^ swz)];
                afr[mt][kb][1] = AS[(r0 + 8) * 32 + (p0 ^ swz)];
                afr[mt][kb][2] = AS[r0 * 32 + ((p0 + 4) ^ swz)];
                afr[mt][kb][3] = AS[(r0 + 8) * 32 + ((p0 + 4) ^ swz)];
            }
        }
    }

    // ---------- q-GEMM: q[rows, 4] = c @ W2c^T ----------
    {
        float aq[2][4];
        #pragma unroll
        for (int mt = 0; mt < 2; mt++)
            #pragma unroll
            for (int q = 0; q < 4; q++) aq[mt][q] = 0.0f;
        const u64* bq = BQ + (g & 3) * 4 + tq;   // lanes g>=4 alias cols 0-3 (unused)
        #pragma unroll
        for (int kb = 0; kb < 4; kb++) {
            u64 b = bq[kb * 16];
            u32 b0 = (u32)b, b1 = (u32)(b >> 32);
            mma16(aq[0], afr[0][kb][0], afr[0][kb][1], afr[0][kb][2], afr[0][kb][3], b0, b1);
            mma16(aq[1], afr[1][kb][0], afr[1][kb][1], afr[1][kb][2], afr[1][kb][3], b0, b1);
        }
        if (tq < 2) {
            float b0 = tq ? by2[0] : bx2[0];
            float b1 = tq ? by2[1] : bx2[1];
            #pragma unroll
            for (int mt = 0; mt < 2; mt++) {
                int r0 = warp * 32 + mt * 16 + g;
                *(u64*)((float*)&QS[r0]     + tq * 2) = pack2(aq[mt][0] + b0, aq[mt][1] + b1);
                *(u64*)((float*)&QS[r0 + 8] + tq * 2) = pack2(aq[mt][2] + b0, aq[mt][3] + b1);
            }
        }
    }
    __syncwarp();

    // rows owned by this thread (quad-redundant)
    int R[4];
    #pragma unroll
    for (int ri = 0; ri < 4; ri++) R[ri] = warp * 32 + ri * 8 + g;

    float cin[4], cup[4], lsum[4];
    #pragma unroll
    for (int ri = 0; ri < 4; ri++) {
        long rr = base + R[ri];
        float2 xy = make_float2(0.f, 0.f);
        if (rr < M) xy = ((const float2*)coords)[rr];
        cin[ri] = xy.x; cup[ri] = xy.y; lsum[ri] = 0.0f;
    }

    const u64 lkA = dup2(LK_A), lkB = dup2(LK_B);
    const u64 ABSM = 0x7FFFFFFF7FFFFFFFull;
    const u64* bpt  = BP + g * 4 + tq;
    const u32* belt = BEXT + g * 4 + tq;

    for (int st = 0; st < 2; st++) {
        const int bpo  = st * 2048;     // BP u64 offset for this stage
        const int noff = st * 128;      // BEXT plane offset

        // extension A fragment: f16x2 per tq of feats [sa,s2a,ca,c2a,1,0,0,0]
        u32 e0[2], e1[2];
        #pragma unroll
        for (int mt = 0; mt < 2; mt++) {
            {
                float a = cin[2 * mt] * 0.1f, sa, ca;
                sincosf(a, &sa, &ca);
                float s2a = 2.0f * sa * ca, c2a = 1.0f - 2.0f * sa * sa;
                float lo = tq == 0 ? sa : (tq == 1 ? ca : (tq == 2 ? 1.0f : 0.0f));
                float hi = tq == 0 ? s2a : (tq == 1 ? c2a : 0.0f);
                e0[mt] = f16x2p(lo, hi);
            }
            {
                float a = cin[2 * mt + 1] * 0.1f, sa, ca;
                sincosf(a, &sa, &ca);
                float s2a = 2.0f * sa * ca, c2a = 1.0f - 2.0f * sa * sa;
                float lo = tq == 0 ? sa : (tq == 1 ? ca : (tq == 2 ? 1.0f : 0.0f));
                float hi = tq == 0 ? s2a : (tq == 1 ? c2a : 0.0f);
                e1[mt] = f16x2p(lo, hi);
            }
        }

        u64 po0[4], po1[4];
        #pragma unroll
        for (int ri = 0; ri < 4; ri++) { po0[ri] = pack2(0.f, 0.f); po1[ri] = po0[ri]; }

        for (int chunk = 0; chunk < 4; chunk++) {
            int nbase = chunk * 4;                // n-tile within stage (0..15)
            float acc[2][4][4];
            #pragma unroll
            for (int mt = 0; mt < 2; mt++)
                #pragma unroll
                for (int nt = 0; nt < 4; nt++)
                    #pragma unroll
                    for (int q = 0; q < 4; q++) acc[mt][nt][q] = 0.0f;

            // K-extension step (sin features + bias), k 8..15 zero
            #pragma unroll
            for (int nt = 0; nt < 4; nt++) {
                u32 be = belt[(noff + (nbase + nt) * 8) * 4];
                mma16(acc[0][nt], e0[0], e1[0], 0u, 0u, be, 0u);
                mma16(acc[1][nt], e0[1], e1[1], 0u, 0u, be, 0u);
            }

            // main: 4 k16-blocks x 8 independent acc chains
            #pragma unroll
            for (int kb = 0; kb < 4; kb++) {
                u64 bfr[4];
                #pragma unroll
                for (int nt = 0; nt < 4; nt++)
                    bfr[nt] = bpt[bpo + kb * 512 + (nbase + nt) * 32];
                #pragma unroll
                for (int nt = 0; nt < 4; nt++) {
                    u32 b0 = (u32)bfr[nt], b1 = (u32)(bfr[nt] >> 32);
                    mma16(acc[0][nt], afr[0][kb][0], afr[0][kb][1], afr[0][kb][2], afr[0][kb][3], b0, b1);
                    mma16(acc[1][nt], afr[1][kb][0], afr[1][kb][1], afr[1][kb][2], afr[1][kb][3], b0, b1);
                }
            }

            // epilogue: leaky + dot into o partials (bias+sin already in acc)
            #pragma unroll
            for (int nt = 0; nt < 4; nt++) {
                int jp = st * 64 + (nbase + nt) * 4 + tq;
                ulonglong2 P = MP2[jp];
                u64 H0 = P.x, H1 = P.y;
                #pragma unroll
                for (int mt = 0; mt < 2; mt++) {
                    #pragma unroll
                    for (int h = 0; h < 2; h++) {
                        int ri = mt * 2 + h;
                        u64 v = pack2(acc[mt][nt][2 * h + 0], acc[mt][nt][2 * h + 1]);
                        u64 av = v & ABSM;
                        u64 hh = ffma2(lkA, v, mul2(lkB, av));
                        po0[ri] = ffma2(hh, H0, po0[ri]);
                        po1[ri] = ffma2(hh, H1, po1[ri]);
                    }
                }
            }
        }

        // reduce + coordinate update
        #pragma unroll
        for (int ri = 0; ri < 4; ri++) {
            float a0, a1, b0, b1;
            unpack2(po0[ri], a0, a1);
            unpack2(po1[ri], b0, b1);
            float o0 = qredf(a0 + a1);
            float o1 = qredf(b0 + b1);
            float4 qv = QS[R[ri]];
            o0 += st ? qv.z : qv.x;
            o1 += st ? qv.w : qv.y;
            float ls = fminf(fmaxf(o0, -5.0f), 5.0f);
            float up_new = cup[ri] * __expf(ls) + o1;
            lsum[ri] += ls;
            cup[ri] = cin[ri];
            cin[ri] = up_new;
        }
    }

    // after stage 1: cin = x_final, cup = y_final. tq==0 lanes store directly.
    if (tq == 0) {
        #pragma unroll
        for (int ri = 0; ri < 4; ri++) {
            long rr = base + R[ri];
            if (rr < M) {
                ((float2*)out)[rr] = make_float2(cin[ri], cup[ri]);
                out[2 * M + rr] = lsum[ri];
            }
        }
    }
}

extern "C" void kernel_launch(void* const* d_in, const int* in_sizes, int n_in,
                              void* d_out, int out_size) {
    const float* coords = (const float*)d_in[0];
    const float* c      = (const float*)d_in[1];
    const float* Wx1    = (const float*)d_in[2];
    const float* bx1    = (const float*)d_in[3];
    const float* Wx2    = (const float*)d_in[4];
    const float* bx2    = (const float*)d_in[5];
    const float* Wy1    = (const float*)d_in[6];
    const float* by1    = (const float*)d_in[7];
    const float* Wy2    = (const float*)d_in[8];
    const float* by2    = (const float*)d_in[9];
    float* out = (float*)d_out;

    long M = (long)in_sizes[1] / 64;
    int grid = (int)((M + 127) / 128);

    cudaFuncSetAttribute(coupling_mma_kernel,
                         cudaFuncAttributeMaxDynamicSharedMemorySize, SMEM_BYTES);
    coupling_mma_kernel<<<grid, THREADS, SMEM_BYTES>>>(coords, c,
                                                       Wx1, bx1, Wx2, bx2,
                                                       Wy1, by1, Wy2, by2,
                                                       out, M);
}

// round 14
// speedup vs baseline: 1.1401x; 1.0176x over previous
#include <cuda_runtime.h>
#include <math.h>
#include <cstdint>

#define THREADS 128

typedef unsigned long long u64;
typedef unsigned int u32;

// ---------------- f32x2 helpers ----------------
__device__ __forceinline__ u64 ffma2(u64 a, u64 b, u64 c) {
    u64 d; asm("fma.rn.f32x2 %0, %1, %2, %3;" : "=l"(d) : "l"(a), "l"(b), "l"(c)); return d;
}
__device__ __forceinline__ u64 mul2(u64 a, u64 b) {
    u64 d; asm("mul.rn.f32x2 %0, %1, %2;" : "=l"(d) : "l"(a), "l"(b)); return d;
}
__device__ __forceinline__ u64 dup2(float x) {
    u64 d; unsigned u = __float_as_uint(x);
    asm("mov.b64 %0, {%1, %2};" : "=l"(d) : "r"(u), "r"(u)); return d;
}
__device__ __forceinline__ u64 pack2(float a, float b) {
    u64 d; asm("mov.b64 %0, {%1, %2};" : "=l"(d) : "r"(__float_as_uint(a)), "r"(__float_as_uint(b))); return d;
}
__device__ __forceinline__ void unpack2(u64 v, float &lo, float &hi) {
    unsigned a, b; asm("mov.b64 {%0, %1}, %2;" : "=r"(a), "=r"(b) : "l"(v));
    lo = __uint_as_float(a); hi = __uint_as_float(b);
}
__device__ __forceinline__ u64 packu(u32 lo, u32 hi) {
    u64 d; asm("mov.b64 %0, {%1, %2};" : "=l"(d) : "r"(lo), "r"(hi)); return d;
}
// pack two f32 -> f16x2 (lo in bits[15:0], hi in bits[31:16])
__device__ __forceinline__ u32 f16x2p(float lo, float hi) {
    u32 r; asm("cvt.rn.f16x2.f32 %0, %1, %2;" : "=r"(r) : "f"(hi), "f"(lo)); return r;
}

// mma.sync m16n8k16 fp16 -> f32 accum (portable sm_80+ path; tensor pipe, 2x tf32 rate)
__device__ __forceinline__ void mma16(float* acc, u32 a0, u32 a1, u32 a2, u32 a3, u32 b0, u32 b1) {
    asm volatile("mma.sync.aligned.m16n8k16.row.col.f32.f16.f16.f32 "
                 "{%0,%1,%2,%3}, {%4,%5,%6,%7}, {%8,%9}, {%0,%1,%2,%3};"
                 : "+f"(acc[0]), "+f"(acc[1]), "+f"(acc[2]), "+f"(acc[3])
                 : "r"(a0), "r"(a1), "r"(a2), "r"(a3), "r"(b0), "r"(b1));
}

__device__ __forceinline__ float qredf(float v) {
    v += __shfl_xor_sync(0xffffffffu, v, 1);
    v += __shfl_xor_sync(0xffffffffu, v, 2);
    return v;
}

// ---------------- smem layout (bytes) — fits 4 CTAs/SM, both stages resident ----------------
#define SM_QS    0        /* float4[128]                         2048 */
#define SM_MP2   2048     /* ulonglong2[128] (H0,H1)             2048 */
#define SM_BQ    4096     /* u64[4kb][4n][4tq]                   512  */
#define SM_BEXT  4608     /* u32[256n][4tq]  f16x2 pairs         4096 */
#define SM_A     8704     /* u32[128row][32] f16x2, xor-swz      16384 */
#define SM_BP    25088    /* u64[2st][4kb][128n][4tq] f16 pairs  32768 */
#define SMEM_BYTES 57856

#define LK_A 0.84852813742385703f  /* 0.6*sqrt(2) */
#define LK_B 0.56568542494923801f  /* 0.4*sqrt(2) */

__global__ __launch_bounds__(THREADS, 4)
void coupling_mma_kernel(const float* __restrict__ coords,
                         const float* __restrict__ c,
                         const float* __restrict__ Wx1, const float* __restrict__ bx1,
                         const float* __restrict__ Wx2, const float* __restrict__ bx2,
                         const float* __restrict__ Wy1, const float* __restrict__ by1,
                         const float* __restrict__ Wy2, const float* __restrict__ by2,
                         float* __restrict__ out, long M)
{
    extern __shared__ char smem[];
    const int tid  = threadIdx.x;
    const int lane = tid & 31;
    const int warp = tid >> 5;
    const int g    = lane >> 2;     // 0..7
    const int tq   = lane & 3;      // 0..3
    const long base = (long)blockIdx.x * 128;

    const float s1 = 1.0f / sqrtf(68.0f);
    const float s2 = 1.0f / sqrtf(192.0f);

    float4* QS = (float4*)(smem + SM_QS);
    ulonglong2* MP2 = (ulonglong2*)(smem + SM_MP2);
    u64*  BQ   = (u64*)(smem + SM_BQ);
    u32*  BEXT = (u32*)(smem + SM_BEXT);
    u32*  AS   = (u32*)(smem + SM_A);
    u64*  BP   = (u64*)(smem + SM_BP);

    // ---------- staging ----------
    // A: c[128 x 64] -> f16 pairs, u32 idx = row*32 + (p ^ ((row&7)<<2)), p = k/2
    #pragma unroll
    for (int i = 0; i < 8; i++) {
        int idx = tid + i * THREADS;          // 0..1023
        int row = idx >> 3;
        int k8  = idx & 7;                    // group of 8 floats
        long gr = base + row;
        float4 v0 = make_float4(0.f, 0.f, 0.f, 0.f), v1 = v0;
        if (gr < M) {
            v0 = *(const float4*)(c + gr * 64 + k8 * 8);
            v1 = *(const float4*)(c + gr * 64 + k8 * 8 + 4);
        }
        uint4 tv = { f16x2p(v0.x, v0.y), f16x2p(v0.z, v0.w),
                     f16x2p(v1.x, v1.y), f16x2p(v1.z, v1.w) };
        *(uint4*)(AS + row * 32 + ((k8 * 4) ^ ((row & 7) << 2))) = tv;
    }
    // BP [st][kb][128n][4tq]: u64 {f16x2(w[k0],w[k0+1]), f16x2(w[k0+8],w[k0+9])},
    // k0 = kb*16 + 2tq, weights prescaled by s1. Both stages staged up-front.
    #pragma unroll
    for (int i = 0; i < 32; i++) {
        int idx = tid + i * THREADS;          // 0..4095
        int t   = idx & 3;
        int n   = (idx >> 2) & 127;
        int kb  = (idx >> 9) & 3;
        int st  = idx >> 11;
        const float* wr = (st ? Wy1 : Wx1) + n * 68 + 4;
        int k0 = kb * 16 + 2 * t;
        float2 wa = *(const float2*)(wr + k0);
        float2 wb = *(const float2*)(wr + k0 + 8);
        BP[idx] = packu(f16x2p(wa.x * s1, wa.y * s1), f16x2p(wb.x * s1, wb.y * s1));
    }
    // BEXT [n][tq]: f16x2 pair (bext[2tq], bext[2tq+1]) with
    // bext = [W1s0,W1s1,W1s2,W1s3 (xs1), b1, 0, 0, 0]
    #pragma unroll
    for (int i = 0; i < 8; i++) {
        int idx = tid + i * THREADS;          // 0..1023
        int n = idx >> 2;
        int t = idx & 3;
        const float* Wg  = (n < 128) ? Wx1 : Wy1;
        const float* b1g = (n < 128) ? bx1 : by1;
        int row = n & 127;
        float lo, hi;
        if (t == 0)      { lo = Wg[row * 68 + 0] * s1; hi = Wg[row * 68 + 1] * s1; }
        else if (t == 1) { lo = Wg[row * 68 + 2] * s1; hi = Wg[row * 68 + 3] * s1; }
        else if (t == 2) { lo = b1g[row];              hi = 0.0f; }
        else             { lo = 0.0f;                  hi = 0.0f; }
        BEXT[idx] = f16x2p(lo, hi);
    }
    // BQ [kb][4n][4tq]: q-GEMM weights (scale s2). col n: 0=qx0,1=qx1,2=qy0,3=qy1
    if (tid < 64) {
        int t  = tid & 3;
        int n  = (tid >> 2) & 3;
        int kb = tid >> 4;
        const float* Wsrc = (n >> 1) ? Wy2 : Wx2;
        const float* wr = Wsrc + (n & 1) * 192 + 128;
        int k0 = kb * 16 + 2 * t;
        BQ[tid] = packu(f16x2p(wr[k0] * s2,     wr[k0 + 1] * s2),
                        f16x2p(wr[k0 + 8] * s2, wr[k0 + 9] * s2));
    }
    // MP2: jp -> (H0, H1) f32 pairs
    {
        int jp = tid;
        int j0 = 2 * jp;
        int st = j0 >> 7;
        int jj0 = j0 & 127, jj1 = jj0 + 1;
        const float* W2g = st ? Wy2 : Wx2;
        ulonglong2 p;
        p.x = pack2(W2g[jj0] * s2, W2g[jj1] * s2);
        p.y = pack2(W2g[192 + jj0] * s2, W2g[192 + jj1] * s2);
        MP2[jp] = p;
    }
    __syncthreads();

    // ---------- A fragments (m16n8k16): afr[mt][kb] = {a0,a1,a2,a3} ----------
    u32 afr[2][4][4];
    {
        const int swz = g << 2;
        #pragma unroll
        for (int mt = 0; mt < 2; mt++) {
            int r0 = warp * 32 + mt * 16 + g;
            #pragma unroll
            for (int kb = 0; kb < 4; kb++) {
                int p0 = kb * 8 + tq;
                afr[mt][kb][0] = AS[r0 * 32 + (p0 ^ swz)];
                afr[mt][kb][1] = AS[(r0 + 8) * 32 + (p0 ^ swz)];
                afr[mt][kb][2] = AS[r0 * 32 + ((p0 + 4) ^ swz)];
                afr[mt][kb][3] = AS[(r0 + 8) * 32 + ((p0 + 4) ^ swz)];
            }
        }
    }

    // ---------- q-GEMM: q[rows, 4] = c @ W2c^T ----------
    {
        float aq[2][4];
        #pragma unroll
        for (int mt = 0; mt < 2; mt++)
            #pragma unroll
            for (int q = 0; q < 4; q++) aq[mt][q] = 0.0f;
        const u64* bq = BQ + (g & 3) * 4 + tq;   // lanes g>=4 alias cols 0-3 (unused)
        #pragma unroll
        for (int kb = 0; kb < 4; kb++) {
            u64 b = bq[kb * 16];
            u32 b0 = (u32)b, b1 = (u32)(b >> 32);
            mma16(aq[0], afr[0][kb][0], afr[0][kb][1], afr[0][kb][2], afr[0][kb][3], b0, b1);
            mma16(aq[1], afr[1][kb][0], afr[1][kb][1], afr[1][kb][2], afr[1][kb][3], b0, b1);
        }
        if (tq < 2) {
            float b0 = tq ? by2[0] : bx2[0];
            float b1 = tq ? by2[1] : bx2[1];
            #pragma unroll
            for (int mt = 0; mt < 2; mt++) {
                int r0 = warp * 32 + mt * 16 + g;
                *(u64*)((float*)&QS[r0]     + tq * 2) = pack2(aq[mt][0] + b0, aq[mt][1] + b1);
                *(u64*)((float*)&QS[r0 + 8] + tq * 2) = pack2(aq[mt][2] + b0, aq[mt][3] + b1);
            }
        }
    }
    __syncwarp();

    // rows owned by this thread (quad-redundant)
    int R[4];
    #pragma unroll
    for (int ri = 0; ri < 4; ri++) R[ri] = warp * 32 + ri * 8 + g;

    float cin[4], cup[4], lsum[4];
    #pragma unroll
    for (int ri = 0; ri < 4; ri++) {
        long rr = base + R[ri];
        float2 xy = make_float2(0.f, 0.f);
        if (rr < M) xy = ((const float2*)coords)[rr];
        cin[ri] = xy.x; cup[ri] = xy.y; lsum[ri] = 0.0f;
    }

    const u64 lkA = dup2(LK_A), lkB = dup2(LK_B);
    const u64 ABSM = 0x7FFFFFFF7FFFFFFFull;
    const u64* bpt  = BP + g * 4 + tq;
    const u32* belt = BEXT + g * 4 + tq;

    for (int st = 0; st < 2; st++) {
        const int bpo  = st * 2048;     // BP u64 offset for this stage
        const int noff = st * 128;      // BEXT plane offset

        // extension A fragment: f16x2 per tq of feats [sa,s2a,ca,c2a,1,0,0,0]
        u32 e0[2], e1[2];
        #pragma unroll
        for (int mt = 0; mt < 2; mt++) {
            {
                float a = cin[2 * mt] * 0.1f, sa, ca;
                sincosf(a, &sa, &ca);
                float s2a = 2.0f * sa * ca, c2a = 1.0f - 2.0f * sa * sa;
                float lo = tq == 0 ? sa : (tq == 1 ? ca : (tq == 2 ? 1.0f : 0.0f));
                float hi = tq == 0 ? s2a : (tq == 1 ? c2a : 0.0f);
                e0[mt] = f16x2p(lo, hi);
            }
            {
                float a = cin[2 * mt + 1] * 0.1f, sa, ca;
                sincosf(a, &sa, &ca);
                float s2a = 2.0f * sa * ca, c2a = 1.0f - 2.0f * sa * sa;
                float lo = tq == 0 ? sa : (tq == 1 ? ca : (tq == 2 ? 1.0f : 0.0f));
                float hi = tq == 0 ? s2a : (tq == 1 ? c2a : 0.0f);
                e1[mt] = f16x2p(lo, hi);
            }
        }

        u64 po0[4], po1[4];
        #pragma unroll
        for (int ri = 0; ri < 4; ri++) { po0[ri] = pack2(0.f, 0.f); po1[ri] = po0[ri]; }

        for (int chunk = 0; chunk < 4; chunk++) {
            int nbase = chunk * 4;                // n-tile within stage (0..15)
            float acc[2][4][4];
            #pragma unroll
            for (int mt = 0; mt < 2; mt++)
                #pragma unroll
                for (int nt = 0; nt < 4; nt++)
                    #pragma unroll
                    for (int q = 0; q < 4; q++) acc[mt][nt][q] = 0.0f;

            // K-extension step (sin features + bias), k 8..15 zero
            #pragma unroll
            for (int nt = 0; nt < 4; nt++) {
                u32 be = belt[(noff + (nbase + nt) * 8) * 4];
                mma16(acc[0][nt], e0[0], e1[0], 0u, 0u, be, 0u);
                mma16(acc[1][nt], e0[1], e1[1], 0u, 0u, be, 0u);
            }

            // main: 4 k16-blocks x 8 independent acc chains
            #pragma unroll
            for (int kb = 0; kb < 4; kb++) {
                u64 bfr[4];
                #pragma unroll
                for (int nt = 0; nt < 4; nt++)
                    bfr[nt] = bpt[bpo + kb * 512 + (nbase + nt) * 32];
                #pragma unroll
                for (int nt = 0; nt < 4; nt++) {
                    u32 b0 = (u32)bfr[nt], b1 = (u32)(bfr[nt] >> 32);
                    mma16(acc[0][nt], afr[0][kb][0], afr[0][kb][1], afr[0][kb][2], afr[0][kb][3], b0, b1);
                    mma16(acc[1][nt], afr[1][kb][0], afr[1][kb][1], afr[1][kb][2], afr[1][kb][3], b0, b1);
                }
            }

            // epilogue: leaky + dot into o partials (bias+sin already in acc)
            #pragma unroll
            for (int nt = 0; nt < 4; nt++) {
                int jp = st * 64 + (nbase + nt) * 4 + tq;
                ulonglong2 P = MP2[jp];
                u64 H0 = P.x, H1 = P.y;
                #pragma unroll
                for (int h = 0; h < 2; h++) {
                    #pragma unroll
                    for (int mt = 0; mt < 2; mt++) {
                        int ri = mt * 2 + h;
                        u64 v = pack2(acc[mt][nt][2 * h + 0], acc[mt][nt][2 * h + 1]);
                        u64 av = v & ABSM;
                        u64 hh = ffma2(lkA, v, mul2(lkB, av));
                        po0[ri] = ffma2(hh, H0, po0[ri]);
                        po1[ri] = ffma2(hh, H1, po1[ri]);
                    }
                }
            }
        }

        // reduce + coordinate update
        #pragma unroll
        for (int ri = 0; ri < 4; ri++) {
            float a0, a1, b0, b1;
            unpack2(po0[ri], a0, a1);
            unpack2(po1[ri], b0, b1);
            float o0 = qredf(a0 + a1);
            float o1 = qredf(b0 + b1);
            float4 qv = QS[R[ri]];
            o0 += st ? qv.z : qv.x;
            o1 += st ? qv.w : qv.y;
            float ls = fminf(fmaxf(o0, -5.0f), 5.0f);
            float up_new = cup[ri] * __expf(ls) + o1;
            lsum[ri] += ls;
            cup[ri] = cin[ri];
            cin[ri] = up_new;
        }
    }

    // after stage 1: cin = x_final, cup = y_final. tq==0 lanes store directly.
    if (tq == 0) {
        #pragma unroll
        for (int ri = 0; ri < 4; ri++) {
            long rr = base + R[ri];
            if (rr < M) {
                ((float2*)out)[rr] = make_float2(cin[ri], cup[ri]);
                out[2 * M + rr] = lsum[ri];
            }
        }
    }
}

extern "C" void kernel_launch(void* const* d_in, const int* in_sizes, int n_in,
                              void* d_out, int out_size) {
    const float* coords = (const float*)d_in[0];
    const float* c      = (const float*)d_in[1];
    const float* Wx1    = (const float*)d_in[2];
    const float* bx1    = (const float*)d_in[3];
    const float* Wx2    = (const float*)d_in[4];
    const float* bx2    = (const float*)d_in[5];
    const float* Wy1    = (const float*)d_in[6];
    const float* by1    = (const float*)d_in[7];
    const float* Wy2    = (const float*)d_in[8];
    const float* by2    = (const float*)d_in[9];
    float* out = (float*)d_out;

    long M = (long)in_sizes[1] / 64;
    int grid = (int)((M + 127) / 128);

    cudaFuncSetAttribute(coupling_mma_kernel,
                         cudaFuncAttributeMaxDynamicSharedMemorySize, SMEM_BYTES);
    coupling_mma_kernel<<<grid, THREADS, SMEM_BYTES>>>(coords, c,
                                                       Wx1, bx1, Wx2, bx2,
                                                       Wy1, by1, Wy2, by2,
                                                       out, M);
}

// round 15
// speedup vs baseline: 1.1714x; 1.0275x over previous
#include <cuda_runtime.h>
#include <math.h>
#include <cstdint>

#define THREADS 128

typedef unsigned long long u64;
typedef unsigned int u32;

// ---------------- f32x2 helpers ----------------
__device__ __forceinline__ u64 ffma2(u64 a, u64 b, u64 c) {
    u64 d; asm("fma.rn.f32x2 %0, %1, %2, %3;" : "=l"(d) : "l"(a), "l"(b), "l"(c)); return d;
}
__device__ __forceinline__ u64 mul2(u64 a, u64 b) {
    u64 d; asm("mul.rn.f32x2 %0, %1, %2;" : "=l"(d) : "l"(a), "l"(b)); return d;
}
__device__ __forceinline__ u64 dup2(float x) {
    u64 d; unsigned u = __float_as_uint(x);
    asm("mov.b64 %0, {%1, %2};" : "=l"(d) : "r"(u), "r"(u)); return d;
}
__device__ __forceinline__ u64 pack2(float a, float b) {
    u64 d; asm("mov.b64 %0, {%1, %2};" : "=l"(d) : "r"(__float_as_uint(a)), "r"(__float_as_uint(b))); return d;
}
__device__ __forceinline__ void unpack2(u64 v, float &lo, float &hi) {
    unsigned a, b; asm("mov.b64 {%0, %1}, %2;" : "=r"(a), "=r"(b) : "l"(v));
    lo = __uint_as_float(a); hi = __uint_as_float(b);
}
__device__ __forceinline__ u64 packu(u32 lo, u32 hi) {
    u64 d; asm("mov.b64 %0, {%1, %2};" : "=l"(d) : "r"(lo), "r"(hi)); return d;
}
// pack two f32 -> f16x2 (lo in bits[15:0], hi in bits[31:16])
__device__ __forceinline__ u32 f16x2p(float lo, float hi) {
    u32 r; asm("cvt.rn.f16x2.f32 %0, %1, %2;" : "=r"(r) : "f"(hi), "f"(lo)); return r;
}

// mma.sync m16n8k16 fp16 -> f32 accum (portable sm_80+ path; tensor pipe, 2x tf32 rate)
__device__ __forceinline__ void mma16(float* acc, u32 a0, u32 a1, u32 a2, u32 a3, u32 b0, u32 b1) {
    asm volatile("mma.sync.aligned.m16n8k16.row.col.f32.f16.f16.f32 "
                 "{%0,%1,%2,%3}, {%4,%5,%6,%7}, {%8,%9}, {%0,%1,%2,%3};"
                 : "+f"(acc[0]), "+f"(acc[1]), "+f"(acc[2]), "+f"(acc[3])
                 : "r"(a0), "r"(a1), "r"(a2), "r"(a3), "r"(b0), "r"(b1));
}

__device__ __forceinline__ float qredf(float v) {
    v += __shfl_xor_sync(0xffffffffu, v, 1);
    v += __shfl_xor_sync(0xffffffffu, v, 2);
    return v;
}

// ---------------- smem layout (bytes) — fits 4 CTAs/SM, both stages resident ----------------
#define SM_QS    0        /* float4[128]                         2048 */
#define SM_MP2   2048     /* ulonglong2[128] (H0,H1)             2048 */
#define SM_BQ    4096     /* u64[4kb][4n][4tq]                   512  */
#define SM_BEXT  4608     /* u32[256n][3tq]  f16x2 pairs         3072 */
#define SM_A     7680     /* u32[128row][32] f16x2, xor-swz      16384 */
#define SM_BP    24064    /* u64[2st][4kb][128n][4tq] f16 pairs  32768 */
#define SMEM_BYTES 56832

#define LK_A 0.84852813742385703f  /* 0.6*sqrt(2) */
#define LK_B 0.56568542494923801f  /* 0.4*sqrt(2) */

__global__ __launch_bounds__(THREADS, 4)
void coupling_mma_kernel(const float* __restrict__ coords,
                         const float* __restrict__ c,
                         const float* __restrict__ Wx1, const float* __restrict__ bx1,
                         const float* __restrict__ Wx2, const float* __restrict__ bx2,
                         const float* __restrict__ Wy1, const float* __restrict__ by1,
                         const float* __restrict__ Wy2, const float* __restrict__ by2,
                         float* __restrict__ out, long M)
{
    extern __shared__ char smem[];
    const int tid  = threadIdx.x;
    const int lane = tid & 31;
    const int warp = tid >> 5;
    const int g    = lane >> 2;     // 0..7
    const int tq   = lane & 3;      // 0..3
    const long base = (long)blockIdx.x * 128;

    const float s1 = 1.0f / sqrtf(68.0f);
    const float s2 = 1.0f / sqrtf(192.0f);

    float4* QS = (float4*)(smem + SM_QS);
    ulonglong2* MP2 = (ulonglong2*)(smem + SM_MP2);
    u64*  BQ   = (u64*)(smem + SM_BQ);
    u32*  BEXT = (u32*)(smem + SM_BEXT);
    u32*  AS   = (u32*)(smem + SM_A);
    u64*  BP   = (u64*)(smem + SM_BP);

    // ---------- staging ----------
    // A: c[128 x 64] -> f16 pairs, u32 idx = row*32 + (p ^ ((row&7)<<2)), p = k/2
    #pragma unroll
    for (int i = 0; i < 8; i++) {
        int idx = tid + i * THREADS;          // 0..1023
        int row = idx >> 3;
        int k8  = idx & 7;                    // group of 8 floats
        long gr = base + row;
        float4 v0 = make_float4(0.f, 0.f, 0.f, 0.f), v1 = v0;
        if (gr < M) {
            v0 = *(const float4*)(c + gr * 64 + k8 * 8);
            v1 = *(const float4*)(c + gr * 64 + k8 * 8 + 4);
        }
        uint4 tv = { f16x2p(v0.x, v0.y), f16x2p(v0.z, v0.w),
                     f16x2p(v1.x, v1.y), f16x2p(v1.z, v1.w) };
        *(uint4*)(AS + row * 32 + ((k8 * 4) ^ ((row & 7) << 2))) = tv;
    }
    // BP [st][kb][128n][4tq]: u64 {f16x2(w[k0],w[k0+1]), f16x2(w[k0+8],w[k0+9])},
    // k0 = kb*16 + 2tq, weights prescaled by s1. Both stages staged up-front.
    #pragma unroll
    for (int i = 0; i < 32; i++) {
        int idx = tid + i * THREADS;          // 0..4095
        int t   = idx & 3;
        int n   = (idx >> 2) & 127;
        int kb  = (idx >> 9) & 3;
        int st  = idx >> 11;
        const float* wr = (st ? Wy1 : Wx1) + n * 68 + 4;
        int k0 = kb * 16 + 2 * t;
        float2 wa = *(const float2*)(wr + k0);
        float2 wb = *(const float2*)(wr + k0 + 8);
        BP[idx] = packu(f16x2p(wa.x * s1, wa.y * s1), f16x2p(wb.x * s1, wb.y * s1));
    }
    // BEXT [n][3]: f16x2 pair (bext[2t], bext[2t+1]), t=0..2, with
    // bext = [W1s0,W1s1,W1s2,W1s3 (xs1), b1, 0]  (t=3 column is all-zero -> dropped)
    #pragma unroll
    for (int i = 0; i < 6; i++) {
        int idx = tid + i * THREADS;          // 0..767
        int n = idx / 3;
        int t = idx - n * 3;
        const float* Wg  = (n < 128) ? Wx1 : Wy1;
        const float* b1g = (n < 128) ? bx1 : by1;
        int row = n & 127;
        float lo, hi;
        if (t == 0)      { lo = Wg[row * 68 + 0] * s1; hi = Wg[row * 68 + 1] * s1; }
        else if (t == 1) { lo = Wg[row * 68 + 2] * s1; hi = Wg[row * 68 + 3] * s1; }
        else             { lo = b1g[row];              hi = 0.0f; }
        BEXT[idx] = f16x2p(lo, hi);
    }
    // BQ [kb][4n][4tq]: q-GEMM weights (scale s2). col n: 0=qx0,1=qx1,2=qy0,3=qy1
    if (tid < 64) {
        int t  = tid & 3;
        int n  = (tid >> 2) & 3;
        int kb = tid >> 4;
        const float* Wsrc = (n >> 1) ? Wy2 : Wx2;
        const float* wr = Wsrc + (n & 1) * 192 + 128;
        int k0 = kb * 16 + 2 * t;
        BQ[tid] = packu(f16x2p(wr[k0] * s2,     wr[k0 + 1] * s2),
                        f16x2p(wr[k0 + 8] * s2, wr[k0 + 9] * s2));
    }
    // MP2: jp -> (H0, H1) f32 pairs
    {
        int jp = tid;
        int j0 = 2 * jp;
        int st = j0 >> 7;
        int jj0 = j0 & 127, jj1 = jj0 + 1;
        const float* W2g = st ? Wy2 : Wx2;
        ulonglong2 p;
        p.x = pack2(W2g[jj0] * s2, W2g[jj1] * s2);
        p.y = pack2(W2g[192 + jj0] * s2, W2g[192 + jj1] * s2);
        MP2[jp] = p;
    }
    __syncthreads();

    // ---------- A fragments (m16n8k16): afr[mt][kb] = {a0,a1,a2,a3} ----------
    u32 afr[2][4][4];
    {
        const int swz = g << 2;
        #pragma unroll
        for (int mt = 0; mt < 2; mt++) {
            int r0 = warp * 32 + mt * 16 + g;
            #pragma unroll
            for (int kb = 0; kb < 4; kb++) {
                int p0 = kb * 8 + tq;
                afr[mt][kb][0] = AS[r0 * 32 + (p0 ^ swz)];
                afr[mt][kb][1] = AS[(r0 + 8) * 32 + (p0 ^ swz)];
                afr[mt][kb][2] = AS[r0 * 32 + ((p0 + 4) ^ swz)];
                afr[mt][kb][3] = AS[(r0 + 8) * 32 + ((p0 + 4) ^ swz)];
            }
        }
    }

    // ---------- q-GEMM: q[rows, 4] = c @ W2c^T ----------
    {
        float aq[2][4];
        #pragma unroll
        for (int mt = 0; mt < 2; mt++)
            #pragma unroll
            for (int q = 0; q < 4; q++) aq[mt][q] = 0.0f;
        const u64* bq = BQ + (g & 3) * 4 + tq;   // lanes g>=4 alias cols 0-3 (unused)
        #pragma unroll
        for (int kb = 0; kb < 4; kb++) {
            u64 b = bq[kb * 16];
            u32 b0 = (u32)b, b1 = (u32)(b >> 32);
            mma16(aq[0], afr[0][kb][0], afr[0][kb][1], afr[0][kb][2], afr[0][kb][3], b0, b1);
            mma16(aq[1], afr[1][kb][0], afr[1][kb][1], afr[1][kb][2], afr[1][kb][3], b0, b1);
        }
        if (tq < 2) {
            float b0 = tq ? by2[0] : bx2[0];
            float b1 = tq ? by2[1] : bx2[1];
            #pragma unroll
            for (int mt = 0; mt < 2; mt++) {
                int r0 = warp * 32 + mt * 16 + g;
                *(u64*)((float*)&QS[r0]     + tq * 2) = pack2(aq[mt][0] + b0, aq[mt][1] + b1);
                *(u64*)((float*)&QS[r0 + 8] + tq * 2) = pack2(aq[mt][2] + b0, aq[mt][3] + b1);
            }
        }
    }
    __syncwarp();

    // rows owned by this thread (quad-redundant)
    int R[4];
    #pragma unroll
    for (int ri = 0; ri < 4; ri++) R[ri] = warp * 32 + ri * 8 + g;

    float cin[4], cup[4], lsum[4];
    #pragma unroll
    for (int ri = 0; ri < 4; ri++) {
        long rr = base + R[ri];
        float2 xy = make_float2(0.f, 0.f);
        if (rr < M) xy = ((const float2*)coords)[rr];
        cin[ri] = xy.x; cup[ri] = xy.y; lsum[ri] = 0.0f;
    }

    const u64 lkA = dup2(LK_A), lkB = dup2(LK_B);
    const u64 ABSM = 0x7FFFFFFF7FFFFFFFull;
    const u64* bpt  = BP + g * 4 + tq;
    const u32* belt = BEXT + g * 3 + tq;     // valid only for tq < 3
    const bool t3 = (tq == 3);

    for (int st = 0; st < 2; st++) {
        const int bpo  = st * 2048;     // BP u64 offset for this stage
        const int noff = st * 128;      // BEXT plane offset

        // extension A fragment: f16x2 per tq of feats [sa,s2a,ca,c2a,1,0,0,0]
        u32 e0[2], e1[2];
        #pragma unroll
        for (int mt = 0; mt < 2; mt++) {
            {
                float a = cin[2 * mt] * 0.1f, sa, ca;
                sincosf(a, &sa, &ca);
                float s2a = 2.0f * sa * ca, c2a = 1.0f - 2.0f * sa * sa;
                float lo = tq == 0 ? sa : (tq == 1 ? ca : (tq == 2 ? 1.0f : 0.0f));
                float hi = tq == 0 ? s2a : (tq == 1 ? c2a : 0.0f);
                e0[mt] = f16x2p(lo, hi);
            }
            {
                float a = cin[2 * mt + 1] * 0.1f, sa, ca;
                sincosf(a, &sa, &ca);
                float s2a = 2.0f * sa * ca, c2a = 1.0f - 2.0f * sa * sa;
                float lo = tq == 0 ? sa : (tq == 1 ? ca : (tq == 2 ? 1.0f : 0.0f));
                float hi = tq == 0 ? s2a : (tq == 1 ? c2a : 0.0f);
                e1[mt] = f16x2p(lo, hi);
            }
        }

        u64 po0[4], po1[4];
        #pragma unroll
        for (int ri = 0; ri < 4; ri++) { po0[ri] = pack2(0.f, 0.f); po1[ri] = po0[ri]; }

        for (int chunk = 0; chunk < 4; chunk++) {
            int nbase = chunk * 4;                // n-tile within stage (0..15)
            float acc[2][4][4];
            #pragma unroll
            for (int mt = 0; mt < 2; mt++)
                #pragma unroll
                for (int nt = 0; nt < 4; nt++)
                    #pragma unroll
                    for (int q = 0; q < 4; q++) acc[mt][nt][q] = 0.0f;

            // K-extension step (sin features + bias), k 8..15 zero; tq=3 column = 0
            #pragma unroll
            for (int nt = 0; nt < 4; nt++) {
                u32 be = t3 ? 0u : belt[(noff + (nbase + nt) * 8) * 3];
                mma16(acc[0][nt], e0[0], e1[0], 0u, 0u, be, 0u);
                mma16(acc[1][nt], e0[1], e1[1], 0u, 0u, be, 0u);
            }

            // main: 4 k16-blocks x 8 independent acc chains
            #pragma unroll
            for (int kb = 0; kb < 4; kb++) {
                u64 bfr[4];
                #pragma unroll
                for (int nt = 0; nt < 4; nt++)
                    bfr[nt] = bpt[bpo + kb * 512 + (nbase + nt) * 32];
                #pragma unroll
                for (int nt = 0; nt < 4; nt++) {
                    u32 b0 = (u32)bfr[nt], b1 = (u32)(bfr[nt] >> 32);
                    mma16(acc[0][nt], afr[0][kb][0], afr[0][kb][1], afr[0][kb][2], afr[0][kb][3], b0, b1);
                    mma16(acc[1][nt], afr[1][kb][0], afr[1][kb][1], afr[1][kb][2], afr[1][kb][3], b0, b1);
                }
            }

            // epilogue: leaky + dot into o partials (bias+sin already in acc)
            #pragma unroll
            for (int nt = 0; nt < 4; nt++) {
                int jp = st * 64 + (nbase + nt) * 4 + tq;
                ulonglong2 P = MP2[jp];
                u64 H0 = P.x, H1 = P.y;
                #pragma unroll
                for (int h = 0; h < 2; h++) {
                    #pragma unroll
                    for (int mt = 0; mt < 2; mt++) {
                        int ri = mt * 2 + h;
                        u64 v = pack2(acc[mt][nt][2 * h + 0], acc[mt][nt][2 * h + 1]);
                        u64 av = v & ABSM;
                        u64 hh = ffma2(lkA, v, mul2(lkB, av));
                        po0[ri] = ffma2(hh, H0, po0[ri]);
                        po1[ri] = ffma2(hh, H1, po1[ri]);
                    }
                }
            }
        }

        // reduce + coordinate update
        #pragma unroll
        for (int ri = 0; ri < 4; ri++) {
            float a0, a1, b0, b1;
            unpack2(po0[ri], a0, a1);
            unpack2(po1[ri], b0, b1);
            float o0 = qredf(a0 + a1);
            float o1 = qredf(b0 + b1);
            float4 qv = QS[R[ri]];
            o0 += st ? qv.z : qv.x;
            o1 += st ? qv.w : qv.y;
            float ls = fminf(fmaxf(o0, -5.0f), 5.0f);
            float up_new = cup[ri] * __expf(ls) + o1;
            lsum[ri] += ls;
            cup[ri] = cin[ri];
            cin[ri] = up_new;
        }
    }

    // after stage 1: cin = x_final, cup = y_final. tq==0 lanes store directly.
    if (tq == 0) {
        #pragma unroll
        for (int ri = 0; ri < 4; ri++) {
            long rr = base + R[ri];
            if (rr < M) {
                ((float2*)out)[rr] = make_float2(cin[ri], cup[ri]);
                out[2 * M + rr] = lsum[ri];
            }
        }
    }
}

extern "C" void kernel_launch(void* const* d_in, const int* in_sizes, int n_in,
                              void* d_out, int out_size) {
    const float* coords = (const float*)d_in[0];
    const float* c      = (const float*)d_in[1];
    const float* Wx1    = (const float*)d_in[2];
    const float* bx1    = (const float*)d_in[3];
    const float* Wx2    = (const float*)d_in[4];
    const float* bx2    = (const float*)d_in[5];
    const float* Wy1    = (const float*)d_in[6];
    const float* by1    = (const float*)d_in[7];
    const float* Wy2    = (const float*)d_in[8];
    const float* by2    = (const float*)d_in[9];
    float* out = (float*)d_out;

    long M = (long)in_sizes[1] / 64;
    int grid = (int)((M + 127) / 128);

    cudaFuncSetAttribute(coupling_mma_kernel,
                         cudaFuncAttributeMaxDynamicSharedMemorySize, SMEM_BYTES);
    coupling_mma_kernel<<<grid, THREADS, SMEM_BYTES>>>(coords, c,
                                                       Wx1, bx1, Wx2, bx2,
                                                       Wy1, by1, Wy2, by2,
                                                       out, M);
}

// round 16
// speedup vs baseline: 1.3219x; 1.1285x over previous
#include <cuda_runtime.h>
#include <math.h>
#include <cstdint>

#define THREADS 128

typedef unsigned long long u64;
typedef unsigned int u32;

// ---------------- f32x2 helpers ----------------
__device__ __forceinline__ u64 ffma2(u64 a, u64 b, u64 c) {
    u64 d; asm("fma.rn.f32x2 %0, %1, %2, %3;" : "=l"(d) : "l"(a), "l"(b), "l"(c)); return d;
}
__device__ __forceinline__ u64 mul2(u64 a, u64 b) {
    u64 d; asm("mul.rn.f32x2 %0, %1, %2;" : "=l"(d) : "l"(a), "l"(b)); return d;
}
__device__ __forceinline__ u64 dup2(float x) {
    u64 d; unsigned u = __float_as_uint(x);
    asm("mov.b64 %0, {%1, %2};" : "=l"(d) : "r"(u), "r"(u)); return d;
}
__device__ __forceinline__ u64 pack2(float a, float b) {
    u64 d; asm("mov.b64 %0, {%1, %2};" : "=l"(d) : "r"(__float_as_uint(a)), "r"(__float_as_uint(b))); return d;
}
__device__ __forceinline__ void unpack2(u64 v, float &lo, float &hi) {
    unsigned a, b; asm("mov.b64 {%0, %1}, %2;" : "=r"(a), "=r"(b) : "l"(v));
    lo = __uint_as_float(a); hi = __uint_as_float(b);
}
__device__ __forceinline__ u64 packu(u32 lo, u32 hi) {
    u64 d; asm("mov.b64 %0, {%1, %2};" : "=l"(d) : "r"(lo), "r"(hi)); return d;
}
// pack two f32 -> f16x2 (lo in bits[15:0], hi in bits[31:16])
__device__ __forceinline__ u32 f16x2p(float lo, float hi) {
    u32 r; asm("cvt.rn.f16x2.f32 %0, %1, %2;" : "=r"(r) : "f"(hi), "f"(lo)); return r;
}

// mma.sync m16n8k16 fp16 -> f32 accum (portable sm_80+ path; tensor pipe, 2x tf32 rate)
__device__ __forceinline__ void mma16(float* acc, u32 a0, u32 a1, u32 a2, u32 a3, u32 b0, u32 b1) {
    asm volatile("mma.sync.aligned.m16n8k16.row.col.f32.f16.f16.f32 "
                 "{%0,%1,%2,%3}, {%4,%5,%6,%7}, {%8,%9}, {%0,%1,%2,%3};"
                 : "+f"(acc[0]), "+f"(acc[1]), "+f"(acc[2]), "+f"(acc[3])
                 : "r"(a0), "r"(a1), "r"(a2), "r"(a3), "r"(b0), "r"(b1));
}

__device__ __forceinline__ float qredf(float v) {
    v += __shfl_xor_sync(0xffffffffu, v, 1);
    v += __shfl_xor_sync(0xffffffffu, v, 2);
    return v;
}

// ---------------- smem layout (bytes) — fits 4 CTAs/SM, both stages resident ----------------
#define SM_QS    0        /* float4[128]                         2048 */
#define SM_MP2   2048     /* ulonglong2[128] (H0,H1)             2048 */
#define SM_BQ    4096     /* u64[4kb][4n][4tq]                   512  */
#define SM_BEXT  4608     /* u32[256n][3tq]  f16x2 pairs         3072 */
#define SM_A     7680     /* u32[128row][32] f16x2, xor-swz      16384 */
#define SM_BP    24064    /* u64[2st][4kb][128n][4tq] f16 pairs  32768 */
#define SMEM_BYTES 56832

#define LK_A 0.84852813742385703f  /* 0.6*sqrt(2) */
#define LK_B 0.56568542494923801f  /* 0.4*sqrt(2) */

__global__ __launch_bounds__(THREADS, 4)
void coupling_mma_kernel(const float* __restrict__ coords,
                         const float* __restrict__ c,
                         const float* __restrict__ Wx1, const float* __restrict__ bx1,
                         const float* __restrict__ Wx2, const float* __restrict__ bx2,
                         const float* __restrict__ Wy1, const float* __restrict__ by1,
                         const float* __restrict__ Wy2, const float* __restrict__ by2,
                         float* __restrict__ out, long M)
{
    extern __shared__ char smem[];
    const int tid  = threadIdx.x;
    const int lane = tid & 31;
    const int warp = tid >> 5;
    const int g    = lane >> 2;     // 0..7
    const int tq   = lane & 3;      // 0..3

    const float s1 = 1.0f / sqrtf(68.0f);
    const float s2 = 1.0f / sqrtf(192.0f);

    float4* QS = (float4*)(smem + SM_QS);
    ulonglong2* MP2 = (ulonglong2*)(smem + SM_MP2);
    u64*  BQ   = (u64*)(smem + SM_BQ);
    u32*  BEXT = (u32*)(smem + SM_BEXT);
    u32*  AS   = (u32*)(smem + SM_A);
    u64*  BP   = (u64*)(smem + SM_BP);

    // ================= weight staging (ONCE per CTA, amortized over 2 row-tiles) =================
    // BP [st][kb][128n][4tq]: u64 {f16x2(w[k0],w[k0+1]), f16x2(w[k0+8],w[k0+9])},
    // k0 = kb*16 + 2tq, weights prescaled by s1. Both stages staged up-front.
    #pragma unroll
    for (int i = 0; i < 32; i++) {
        int idx = tid + i * THREADS;          // 0..4095
        int t   = idx & 3;
        int n   = (idx >> 2) & 127;
        int kb  = (idx >> 9) & 3;
        int st  = idx >> 11;
        const float* wr = (st ? Wy1 : Wx1) + n * 68 + 4;
        int k0 = kb * 16 + 2 * t;
        float2 wa = *(const float2*)(wr + k0);
        float2 wb = *(const float2*)(wr + k0 + 8);
        BP[idx] = packu(f16x2p(wa.x * s1, wa.y * s1), f16x2p(wb.x * s1, wb.y * s1));
    }
    // BEXT [n][3]: f16x2 pair (bext[2t], bext[2t+1]), t=0..2, with
    // bext = [W1s0,W1s1,W1s2,W1s3 (xs1), b1, 0]  (t=3 column is all-zero -> dropped)
    #pragma unroll
    for (int i = 0; i < 6; i++) {
        int idx = tid + i * THREADS;          // 0..767
        int n = idx / 3;
        int t = idx - n * 3;
        const float* Wg  = (n < 128) ? Wx1 : Wy1;
        const float* b1g = (n < 128) ? bx1 : by1;
        int row = n & 127;
        float lo, hi;
        if (t == 0)      { lo = Wg[row * 68 + 0] * s1; hi = Wg[row * 68 + 1] * s1; }
        else if (t == 1) { lo = Wg[row * 68 + 2] * s1; hi = Wg[row * 68 + 3] * s1; }
        else             { lo = b1g[row];              hi = 0.0f; }
        BEXT[idx] = f16x2p(lo, hi);
    }
    // BQ [kb][4n][4tq]: q-GEMM weights (scale s2). col n: 0=qx0,1=qx1,2=qy0,3=qy1
    if (tid < 64) {
        int t  = tid & 3;
        int n  = (tid >> 2) & 3;
        int kb = tid >> 4;
        const float* Wsrc = (n >> 1) ? Wy2 : Wx2;
        const float* wr = Wsrc + (n & 1) * 192 + 128;
        int k0 = kb * 16 + 2 * t;
        BQ[tid] = packu(f16x2p(wr[k0] * s2,     wr[k0 + 1] * s2),
                        f16x2p(wr[k0 + 8] * s2, wr[k0 + 9] * s2));
    }
    // MP2: jp -> (H0, H1) f32 pairs
    {
        int jp = tid;
        int j0 = 2 * jp;
        int st = j0 >> 7;
        int jj0 = j0 & 127, jj1 = jj0 + 1;
        const float* W2g = st ? Wy2 : Wx2;
        ulonglong2 p;
        p.x = pack2(W2g[jj0] * s2, W2g[jj1] * s2);
        p.y = pack2(W2g[192 + jj0] * s2, W2g[192 + jj1] * s2);
        MP2[jp] = p;
    }

    // rows owned by this thread (quad-redundant), constant across tiles
    int R[4];
    #pragma unroll
    for (int ri = 0; ri < 4; ri++) R[ri] = warp * 32 + ri * 8 + g;

    const u64 lkA = dup2(LK_A), lkB = dup2(LK_B);
    const u64 ABSM = 0x7FFFFFFF7FFFFFFFull;
    const u64* bpt  = BP + g * 4 + tq;
    const u32* belt = BEXT + g * 3 + tq;     // valid only for tq < 3
    const bool t3 = (tq == 3);

    // ================= two row-tiles per CTA =================
    #pragma unroll 1
    for (int tile = 0; tile < 2; tile++) {
        const long base = (long)blockIdx.x * 256 + (long)tile * 128;

        // ---- A staging: c[128 x 64] -> f16 pairs, row*32 + (p ^ ((row&7)<<2)) ----
        // (tile 1: AS overwrite is safe — post-afr barrier below guarantees all
        //  warps finished reading tile 0's A.)
        #pragma unroll
        for (int i = 0; i < 8; i++) {
            int idx = tid + i * THREADS;      // 0..1023
            int row = idx >> 3;
            int k8  = idx & 7;
            long gr = base + row;
            float4 v0 = make_float4(0.f, 0.f, 0.f, 0.f), v1 = v0;
            if (gr < M) {
                v0 = *(const float4*)(c + gr * 64 + k8 * 8);
                v1 = *(const float4*)(c + gr * 64 + k8 * 8 + 4);
            }
            uint4 tv = { f16x2p(v0.x, v0.y), f16x2p(v0.z, v0.w),
                         f16x2p(v1.x, v1.y), f16x2p(v1.z, v1.w) };
            *(uint4*)(AS + row * 32 + ((k8 * 4) ^ ((row & 7) << 2))) = tv;
        }
        __syncthreads();    // staging (weights on tile 0 + A) visible

        // ---- A fragments (m16n8k16): afr[mt][kb] = {a0,a1,a2,a3} ----
        u32 afr[2][4][4];
        {
            const int swz = g << 2;
            #pragma unroll
            for (int mt = 0; mt < 2; mt++) {
                int r0 = warp * 32 + mt * 16 + g;
                #pragma unroll
                for (int kb = 0; kb < 4; kb++) {
                    int p0 = kb * 8 + tq;
                    afr[mt][kb][0] = AS[r0 * 32 + (p0 ^ swz)];
                    afr[mt][kb][1] = AS[(r0 + 8) * 32 + (p0 ^ swz)];
                    afr[mt][kb][2] = AS[r0 * 32 + ((p0 + 4) ^ swz)];
                    afr[mt][kb][3] = AS[(r0 + 8) * 32 + ((p0 + 4) ^ swz)];
                }
            }
        }
        __syncthreads();    // all afr loaded -> next tile may overwrite AS

        // ---- q-GEMM: q[rows, 4] = c @ W2c^T ----
        {
            float aq[2][4];
            #pragma unroll
            for (int mt = 0; mt < 2; mt++)
                #pragma unroll
                for (int q = 0; q < 4; q++) aq[mt][q] = 0.0f;
            const u64* bq = BQ + (g & 3) * 4 + tq;   // lanes g>=4 alias cols 0-3 (unused)
            #pragma unroll
            for (int kb = 0; kb < 4; kb++) {
                u64 b = bq[kb * 16];
                u32 b0 = (u32)b, b1 = (u32)(b >> 32);
                mma16(aq[0], afr[0][kb][0], afr[0][kb][1], afr[0][kb][2], afr[0][kb][3], b0, b1);
                mma16(aq[1], afr[1][kb][0], afr[1][kb][1], afr[1][kb][2], afr[1][kb][3], b0, b1);
            }
            if (tq < 2) {
                float b0 = tq ? by2[0] : bx2[0];
                float b1 = tq ? by2[1] : bx2[1];
                #pragma unroll
                for (int mt = 0; mt < 2; mt++) {
                    int r0 = warp * 32 + mt * 16 + g;
                    *(u64*)((float*)&QS[r0]     + tq * 2) = pack2(aq[mt][0] + b0, aq[mt][1] + b1);
                    *(u64*)((float*)&QS[r0 + 8] + tq * 2) = pack2(aq[mt][2] + b0, aq[mt][3] + b1);
                }
            }
        }
        __syncwarp();       // QS rows are warp-local

        float cin[4], cup[4], lsum[4];
        #pragma unroll
        for (int ri = 0; ri < 4; ri++) {
            long rr = base + R[ri];
            float2 xy = make_float2(0.f, 0.f);
            if (rr < M) xy = ((const float2*)coords)[rr];
            cin[ri] = xy.x; cup[ri] = xy.y; lsum[ri] = 0.0f;
        }

        for (int st = 0; st < 2; st++) {
            const int bpo  = st * 2048;     // BP u64 offset for this stage
            const int noff = st * 128;      // BEXT plane offset

            // extension A fragment: f16x2 per tq of feats [sa,s2a,ca,c2a,1,0,0,0]
            u32 e0[2], e1[2];
            #pragma unroll
            for (int mt = 0; mt < 2; mt++) {
                {
                    float a = cin[2 * mt] * 0.1f, sa, ca;
                    sincosf(a, &sa, &ca);
                    float s2a = 2.0f * sa * ca, c2a = 1.0f - 2.0f * sa * sa;
                    float lo = tq == 0 ? sa : (tq == 1 ? ca : (tq == 2 ? 1.0f : 0.0f));
                    float hi = tq == 0 ? s2a : (tq == 1 ? c2a : 0.0f);
                    e0[mt] = f16x2p(lo, hi);
                }
                {
                    float a = cin[2 * mt + 1] * 0.1f, sa, ca;
                    sincosf(a, &sa, &ca);
                    float s2a = 2.0f * sa * ca, c2a = 1.0f - 2.0f * sa * sa;
                    float lo = tq == 0 ? sa : (tq == 1 ? ca : (tq == 2 ? 1.0f : 0.0f));
                    float hi = tq == 0 ? s2a : (tq == 1 ? c2a : 0.0f);
                    e1[mt] = f16x2p(lo, hi);
                }
            }

            u64 po0[4], po1[4];
            #pragma unroll
            for (int ri = 0; ri < 4; ri++) { po0[ri] = pack2(0.f, 0.f); po1[ri] = po0[ri]; }

            for (int chunk = 0; chunk < 4; chunk++) {
                int nbase = chunk * 4;                // n-tile within stage (0..15)
                float acc[2][4][4];
                #pragma unroll
                for (int mt = 0; mt < 2; mt++)
                    #pragma unroll
                    for (int nt = 0; nt < 4; nt++)
                        #pragma unroll
                        for (int q = 0; q < 4; q++) acc[mt][nt][q] = 0.0f;

                // K-extension step (sin features + bias), k 8..15 zero; tq=3 column = 0
                #pragma unroll
                for (int nt = 0; nt < 4; nt++) {
                    u32 be = t3 ? 0u : belt[(noff + (nbase + nt) * 8) * 3];
                    mma16(acc[0][nt], e0[0], e1[0], 0u, 0u, be, 0u);
                    mma16(acc[1][nt], e0[1], e1[1], 0u, 0u, be, 0u);
                }

                // main: 4 k16-blocks x 8 independent acc chains
                #pragma unroll
                for (int kb = 0; kb < 4; kb++) {
                    u64 bfr[4];
                    #pragma unroll
                    for (int nt = 0; nt < 4; nt++)
                        bfr[nt] = bpt[bpo + kb * 512 + (nbase + nt) * 32];
                    #pragma unroll
                    for (int nt = 0; nt < 4; nt++) {
                        u32 b0 = (u32)bfr[nt], b1 = (u32)(bfr[nt] >> 32);
                        mma16(acc[0][nt], afr[0][kb][0], afr[0][kb][1], afr[0][kb][2], afr[0][kb][3], b0, b1);
                        mma16(acc[1][nt], afr[1][kb][0], afr[1][kb][1], afr[1][kb][2], afr[1][kb][3], b0, b1);
                    }
                }

                // epilogue: leaky + dot into o partials (bias+sin already in acc)
                #pragma unroll
                for (int nt = 0; nt < 4; nt++) {
                    int jp = st * 64 + (nbase + nt) * 4 + tq;
                    ulonglong2 P = MP2[jp];
                    u64 H0 = P.x, H1 = P.y;
                    #pragma unroll
                    for (int h = 0; h < 2; h++) {
                        #pragma unroll
                        for (int mt = 0; mt < 2; mt++) {
                            int ri = mt * 2 + h;
                            u64 v = pack2(acc[mt][nt][2 * h + 0], acc[mt][nt][2 * h + 1]);
                            u64 av = v & ABSM;
                            u64 hh = ffma2(lkA, v, mul2(lkB, av));
                            po0[ri] = ffma2(hh, H0, po0[ri]);
                            po1[ri] = ffma2(hh, H1, po1[ri]);
                        }
                    }
                }
            }

            // reduce + coordinate update
            #pragma unroll
            for (int ri = 0; ri < 4; ri++) {
                float a0, a1, b0, b1;
                unpack2(po0[ri], a0, a1);
                unpack2(po1[ri], b0, b1);
                float o0 = qredf(a0 + a1);
                float o1 = qredf(b0 + b1);
                float4 qv = QS[R[ri]];
                o0 += st ? qv.z : qv.x;
                o1 += st ? qv.w : qv.y;
                float ls = fminf(fmaxf(o0, -5.0f), 5.0f);
                float up_new = cup[ri] * __expf(ls) + o1;
                lsum[ri] += ls;
                cup[ri] = cin[ri];
                cin[ri] = up_new;
            }
        }

        // after stage 1: cin = x_final, cup = y_final. tq==0 lanes store directly.
        if (tq == 0) {
            #pragma unroll
            for (int ri = 0; ri < 4; ri++) {
                long rr = base + R[ri];
                if (rr < M) {
                    ((float2*)out)[rr] = make_float2(cin[ri], cup[ri]);
                    out[2 * M + rr] = lsum[ri];
                }
            }
        }
    }
}

extern "C" void kernel_launch(void* const* d_in, const int* in_sizes, int n_in,
                              void* d_out, int out_size) {
    const float* coords = (const float*)d_in[0];
    const float* c      = (const float*)d_in[1];
    const float* Wx1    = (const float*)d_in[2];
    const float* bx1    = (const float*)d_in[3];
    const float* Wx2    = (const float*)d_in[4];
    const float* bx2    = (const float*)d_in[5];
    const float* Wy1    = (const float*)d_in[6];
    const float* by1    = (const float*)d_in[7];
    const float* Wy2    = (const float*)d_in[8];
    const float* by2    = (const float*)d_in[9];
    float* out = (float*)d_out;

    long M = (long)in_sizes[1] / 64;
    int grid = (int)((M + 255) / 256);

    cudaFuncSetAttribute(coupling_mma_kernel,
                         cudaFuncAttributeMaxDynamicSharedMemorySize, SMEM_BYTES);
    coupling_mma_kernel<<<grid, THREADS, SMEM_BYTES>>>(coords, c,
                                                       Wx1, bx1, Wx2, bx2,
                                                       Wy1, by1, Wy2, by2,
                                                       out, M);
}

// round 17
// speedup vs baseline: 1.4417x; 1.0906x over previous
#include <cuda_runtime.h>
#include <math.h>
#include <cstdint>

#define THREADS 128
#define TILES   4

typedef unsigned long long u64;
typedef unsigned int u32;

// ---------------- f32x2 helpers ----------------
__device__ __forceinline__ u64 ffma2(u64 a, u64 b, u64 c) {
    u64 d; asm("fma.rn.f32x2 %0, %1, %2, %3;" : "=l"(d) : "l"(a), "l"(b), "l"(c)); return d;
}
__device__ __forceinline__ u64 mul2(u64 a, u64 b) {
    u64 d; asm("mul.rn.f32x2 %0, %1, %2;" : "=l"(d) : "l"(a), "l"(b)); return d;
}
__device__ __forceinline__ u64 dup2(float x) {
    u64 d; unsigned u = __float_as_uint(x);
    asm("mov.b64 %0, {%1, %2};" : "=l"(d) : "r"(u), "r"(u)); return d;
}
__device__ __forceinline__ u64 pack2(float a, float b) {
    u64 d; asm("mov.b64 %0, {%1, %2};" : "=l"(d) : "r"(__float_as_uint(a)), "r"(__float_as_uint(b))); return d;
}
__device__ __forceinline__ void unpack2(u64 v, float &lo, float &hi) {
    unsigned a, b; asm("mov.b64 {%0, %1}, %2;" : "=r"(a), "=r"(b) : "l"(v));
    lo = __uint_as_float(a); hi = __uint_as_float(b);
}
__device__ __forceinline__ u64 packu(u32 lo, u32 hi) {
    u64 d; asm("mov.b64 %0, {%1, %2};" : "=l"(d) : "r"(lo), "r"(hi)); return d;
}
// pack two f32 -> f16x2 (lo in bits[15:0], hi in bits[31:16])
__device__ __forceinline__ u32 f16x2p(float lo, float hi) {
    u32 r; asm("cvt.rn.f16x2.f32 %0, %1, %2;" : "=r"(r) : "f"(hi), "f"(lo)); return r;
}

// mma.sync m16n8k16 fp16 -> f32 accum (portable sm_80+ path; tensor pipe, 2x tf32 rate)
__device__ __forceinline__ void mma16(float* acc, u32 a0, u32 a1, u32 a2, u32 a3, u32 b0, u32 b1) {
    asm volatile("mma.sync.aligned.m16n8k16.row.col.f32.f16.f16.f32 "
                 "{%0,%1,%2,%3}, {%4,%5,%6,%7}, {%8,%9}, {%0,%1,%2,%3};"
                 : "+f"(acc[0]), "+f"(acc[1]), "+f"(acc[2]), "+f"(acc[3])
                 : "r"(a0), "r"(a1), "r"(a2), "r"(a3), "r"(b0), "r"(b1));
}

__device__ __forceinline__ float qredf(float v) {
    v += __shfl_xor_sync(0xffffffffu, v, 1);
    v += __shfl_xor_sync(0xffffffffu, v, 2);
    return v;
}

// ---------------- smem layout (bytes) — fits 4 CTAs/SM, both stages resident ----------------
#define SM_QS    0        /* float4[128]                         2048 */
#define SM_MP2   2048     /* ulonglong2[128] (H0,H1)             2048 */
#define SM_BQ    4096     /* u64[4kb][4n][4tq]                   512  */
#define SM_BEXT  4608     /* u32[256n][3tq]  f16x2 pairs         3072 */
#define SM_A     7680     /* u32[128row][32] f16x2, xor-swz      16384 */
#define SM_BP    24064    /* u64[2st][4kb][128n][4tq] f16 pairs  32768 */
#define SMEM_BYTES 56832

#define LK_A 0.84852813742385703f  /* 0.6*sqrt(2) */
#define LK_B 0.56568542494923801f  /* 0.4*sqrt(2) */

__global__ __launch_bounds__(THREADS, 4)
void coupling_mma_kernel(const float* __restrict__ coords,
                         const float* __restrict__ c,
                         const float* __restrict__ Wx1, const float* __restrict__ bx1,
                         const float* __restrict__ Wx2, const float* __restrict__ bx2,
                         const float* __restrict__ Wy1, const float* __restrict__ by1,
                         const float* __restrict__ Wy2, const float* __restrict__ by2,
                         float* __restrict__ out, long M)
{
    extern __shared__ char smem[];
    const int tid  = threadIdx.x;
    const int lane = tid & 31;
    const int warp = tid >> 5;
    const int g    = lane >> 2;     // 0..7
    const int tq   = lane & 3;      // 0..3

    const float s1 = 1.0f / sqrtf(68.0f);
    const float s2 = 1.0f / sqrtf(192.0f);

    float4* QS = (float4*)(smem + SM_QS);
    ulonglong2* MP2 = (ulonglong2*)(smem + SM_MP2);
    u64*  BQ   = (u64*)(smem + SM_BQ);
    u32*  BEXT = (u32*)(smem + SM_BEXT);
    u32*  AS   = (u32*)(smem + SM_A);
    u64*  BP   = (u64*)(smem + SM_BP);

    // ================= weight staging (ONCE per CTA, amortized over TILES row-tiles) =================
    // BP [st][kb][128n][4tq]: u64 {f16x2(w[k0],w[k0+1]), f16x2(w[k0+8],w[k0+9])},
    // k0 = kb*16 + 2tq, weights prescaled by s1. Both stages staged up-front.
    #pragma unroll
    for (int i = 0; i < 32; i++) {
        int idx = tid + i * THREADS;          // 0..4095
        int t   = idx & 3;
        int n   = (idx >> 2) & 127;
        int kb  = (idx >> 9) & 3;
        int st  = idx >> 11;
        const float* wr = (st ? Wy1 : Wx1) + n * 68 + 4;
        int k0 = kb * 16 + 2 * t;
        float2 wa = *(const float2*)(wr + k0);
        float2 wb = *(const float2*)(wr + k0 + 8);
        BP[idx] = packu(f16x2p(wa.x * s1, wa.y * s1), f16x2p(wb.x * s1, wb.y * s1));
    }
    // BEXT [n][3]: f16x2 pair (bext[2t], bext[2t+1]), t=0..2, with
    // bext = [W1s0,W1s1,W1s2,W1s3 (xs1), b1, 0]  (t=3 column is all-zero -> dropped)
    #pragma unroll
    for (int i = 0; i < 6; i++) {
        int idx = tid + i * THREADS;          // 0..767
        int n = idx / 3;
        int t = idx - n * 3;
        const float* Wg  = (n < 128) ? Wx1 : Wy1;
        const float* b1g = (n < 128) ? bx1 : by1;
        int row = n & 127;
        float lo, hi;
        if (t == 0)      { lo = Wg[row * 68 + 0] * s1; hi = Wg[row * 68 + 1] * s1; }
        else if (t == 1) { lo = Wg[row * 68 + 2] * s1; hi = Wg[row * 68 + 3] * s1; }
        else             { lo = b1g[row];              hi = 0.0f; }
        BEXT[idx] = f16x2p(lo, hi);
    }
    // BQ [kb][4n][4tq]: q-GEMM weights (scale s2). col n: 0=qx0,1=qx1,2=qy0,3=qy1
    if (tid < 64) {
        int t  = tid & 3;
        int n  = (tid >> 2) & 3;
        int kb = tid >> 4;
        const float* Wsrc = (n >> 1) ? Wy2 : Wx2;
        const float* wr = Wsrc + (n & 1) * 192 + 128;
        int k0 = kb * 16 + 2 * t;
        BQ[tid] = packu(f16x2p(wr[k0] * s2,     wr[k0 + 1] * s2),
                        f16x2p(wr[k0 + 8] * s2, wr[k0 + 9] * s2));
    }
    // MP2: jp -> (H0, H1) f32 pairs
    {
        int jp = tid;
        int j0 = 2 * jp;
        int st = j0 >> 7;
        int jj0 = j0 & 127, jj1 = jj0 + 1;
        const float* W2g = st ? Wy2 : Wx2;
        ulonglong2 p;
        p.x = pack2(W2g[jj0] * s2, W2g[jj1] * s2);
        p.y = pack2(W2g[192 + jj0] * s2, W2g[192 + jj1] * s2);
        MP2[jp] = p;
    }

    // rows owned by this thread (quad-redundant), constant across tiles
    int R[4];
    #pragma unroll
    for (int ri = 0; ri < 4; ri++) R[ri] = warp * 32 + ri * 8 + g;

    const u64 lkA = dup2(LK_A), lkB = dup2(LK_B);
    const u64 ABSM = 0x7FFFFFFF7FFFFFFFull;
    const u64* bpt  = BP + g * 4 + tq;
    const u32* belt = BEXT + g * 3 + tq;     // valid only for tq < 3
    const bool t3 = (tq == 3);
    const float qb0x = bx2[0], qb1x = bx2[1];   // uniform biases, hoisted
    const float qb0y = by2[0], qb1y = by2[1];

    // ================= TILES row-tiles per CTA =================
    #pragma unroll 1
    for (int tile = 0; tile < TILES; tile++) {
        const long base = (long)blockIdx.x * (128L * TILES) + (long)tile * 128;

        // ---- A staging: c[128 x 64] -> f16 pairs, row*32 + (p ^ ((row&7)<<2)) ----
        // (tiles >0: AS overwrite safe — post-afr barrier guarantees prior reads done.)
        #pragma unroll
        for (int i = 0; i < 8; i++) {
            int idx = tid + i * THREADS;      // 0..1023
            int row = idx >> 3;
            int k8  = idx & 7;
            long gr = base + row;
            float4 v0 = make_float4(0.f, 0.f, 0.f, 0.f), v1 = v0;
            if (gr < M) {
                v0 = *(const float4*)(c + gr * 64 + k8 * 8);
                v1 = *(const float4*)(c + gr * 64 + k8 * 8 + 4);
            }
            uint4 tv = { f16x2p(v0.x, v0.y), f16x2p(v0.z, v0.w),
                         f16x2p(v1.x, v1.y), f16x2p(v1.z, v1.w) };
            *(uint4*)(AS + row * 32 + ((k8 * 4) ^ ((row & 7) << 2))) = tv;
        }
        __syncthreads();    // staging (weights on tile 0 + A) visible

        // ---- A fragments (m16n8k16): afr[mt][kb] = {a0,a1,a2,a3} ----
        u32 afr[2][4][4];
        {
            const int swz = g << 2;
            #pragma unroll
            for (int mt = 0; mt < 2; mt++) {
                int r0 = warp * 32 + mt * 16 + g;
                #pragma unroll
                for (int kb = 0; kb < 4; kb++) {
                    int p0 = kb * 8 + tq;
                    afr[mt][kb][0] = AS[r0 * 32 + (p0 ^ swz)];
                    afr[mt][kb][1] = AS[(r0 + 8) * 32 + (p0 ^ swz)];
                    afr[mt][kb][2] = AS[r0 * 32 + ((p0 + 4) ^ swz)];
                    afr[mt][kb][3] = AS[(r0 + 8) * 32 + ((p0 + 4) ^ swz)];
                }
            }
        }
        __syncthreads();    // all afr loaded -> next tile may overwrite AS

        // ---- q-GEMM: q[rows, 4] = c @ W2c^T ----
        {
            float aq[2][4];
            #pragma unroll
            for (int mt = 0; mt < 2; mt++)
                #pragma unroll
                for (int q = 0; q < 4; q++) aq[mt][q] = 0.0f;
            const u64* bq = BQ + (g & 3) * 4 + tq;   // lanes g>=4 alias cols 0-3 (unused)
            #pragma unroll
            for (int kb = 0; kb < 4; kb++) {
                u64 b = bq[kb * 16];
                u32 b0 = (u32)b, b1 = (u32)(b >> 32);
                mma16(aq[0], afr[0][kb][0], afr[0][kb][1], afr[0][kb][2], afr[0][kb][3], b0, b1);
                mma16(aq[1], afr[1][kb][0], afr[1][kb][1], afr[1][kb][2], afr[1][kb][3], b0, b1);
            }
            if (tq < 2) {
                float b0 = tq ? qb0y : qb0x;
                float b1 = tq ? qb1y : qb1x;
                #pragma unroll
                for (int mt = 0; mt < 2; mt++) {
                    int r0 = warp * 32 + mt * 16 + g;
                    *(u64*)((float*)&QS[r0]     + tq * 2) = pack2(aq[mt][0] + b0, aq[mt][1] + b1);
                    *(u64*)((float*)&QS[r0 + 8] + tq * 2) = pack2(aq[mt][2] + b0, aq[mt][3] + b1);
                }
            }
        }
        __syncwarp();       // QS rows are warp-local

        float cin[4], cup[4], lsum[4];
        #pragma unroll
        for (int ri = 0; ri < 4; ri++) {
            long rr = base + R[ri];
            float2 xy = make_float2(0.f, 0.f);
            if (rr < M) xy = ((const float2*)coords)[rr];
            cin[ri] = xy.x; cup[ri] = xy.y; lsum[ri] = 0.0f;
        }

        for (int st = 0; st < 2; st++) {
            const int bpo  = st * 2048;     // BP u64 offset for this stage
            const int noff = st * 128;      // BEXT plane offset

            // extension A fragment: f16x2 per tq of feats [sa,s2a,ca,c2a,1,0,0,0]
            u32 e0[2], e1[2];
            #pragma unroll
            for (int mt = 0; mt < 2; mt++) {
                {
                    float a = cin[2 * mt] * 0.1f, sa, ca;
                    sincosf(a, &sa, &ca);
                    float s2a = 2.0f * sa * ca, c2a = 1.0f - 2.0f * sa * sa;
                    float lo = tq == 0 ? sa : (tq == 1 ? ca : (tq == 2 ? 1.0f : 0.0f));
                    float hi = tq == 0 ? s2a : (tq == 1 ? c2a : 0.0f);
                    e0[mt] = f16x2p(lo, hi);
                }
                {
                    float a = cin[2 * mt + 1] * 0.1f, sa, ca;
                    sincosf(a, &sa, &ca);
                    float s2a = 2.0f * sa * ca, c2a = 1.0f - 2.0f * sa * sa;
                    float lo = tq == 0 ? sa : (tq == 1 ? ca : (tq == 2 ? 1.0f : 0.0f));
                    float hi = tq == 0 ? s2a : (tq == 1 ? c2a : 0.0f);
                    e1[mt] = f16x2p(lo, hi);
                }
            }

            u64 po0[4], po1[4];
            #pragma unroll
            for (int ri = 0; ri < 4; ri++) { po0[ri] = pack2(0.f, 0.f); po1[ri] = po0[ri]; }

            for (int chunk = 0; chunk < 4; chunk++) {
                int nbase = chunk * 4;                // n-tile within stage (0..15)
                float acc[2][4][4];
                #pragma unroll
                for (int mt = 0; mt < 2; mt++)
                    #pragma unroll
                    for (int nt = 0; nt < 4; nt++)
                        #pragma unroll
                        for (int q = 0; q < 4; q++) acc[mt][nt][q] = 0.0f;

                // K-extension step (sin features + bias), k 8..15 zero; tq=3 column = 0
                #pragma unroll
                for (int nt = 0; nt < 4; nt++) {
                    u32 be = t3 ? 0u : belt[(noff + (nbase + nt) * 8) * 3];
                    mma16(acc[0][nt], e0[0], e1[0], 0u, 0u, be, 0u);
                    mma16(acc[1][nt], e0[1], e1[1], 0u, 0u, be, 0u);
                }

                // main: 4 k16-blocks x 8 independent acc chains
                #pragma unroll
                for (int kb = 0; kb < 4; kb++) {
                    u64 bfr[4];
                    #pragma unroll
                    for (int nt = 0; nt < 4; nt++)
                        bfr[nt] = bpt[bpo + kb * 512 + (nbase + nt) * 32];
                    #pragma unroll
                    for (int nt = 0; nt < 4; nt++) {
                        u32 b0 = (u32)bfr[nt], b1 = (u32)(bfr[nt] >> 32);
                        mma16(acc[0][nt], afr[0][kb][0], afr[0][kb][1], afr[0][kb][2], afr[0][kb][3], b0, b1);
                        mma16(acc[1][nt], afr[1][kb][0], afr[1][kb][1], afr[1][kb][2], afr[1][kb][3], b0, b1);
                    }
                }

                // epilogue: leaky + dot into o partials (bias+sin already in acc)
                #pragma unroll
                for (int nt = 0; nt < 4; nt++) {
                    int jp = st * 64 + (nbase + nt) * 4 + tq;
                    ulonglong2 P = MP2[jp];
                    u64 H0 = P.x, H1 = P.y;
                    #pragma unroll
                    for (int h = 0; h < 2; h++) {
                        #pragma unroll
                        for (int mt = 0; mt < 2; mt++) {
                            int ri = mt * 2 + h;
                            u64 v = pack2(acc[mt][nt][2 * h + 0], acc[mt][nt][2 * h + 1]);
                            u64 av = v & ABSM;
                            u64 hh = ffma2(lkA, v, mul2(lkB, av));
                            po0[ri] = ffma2(hh, H0, po0[ri]);
                            po1[ri] = ffma2(hh, H1, po1[ri]);
                        }
                    }
                }
            }

            // reduce + coordinate update
            #pragma unroll
            for (int ri = 0; ri < 4; ri++) {
                float a0, a1, b0, b1;
                unpack2(po0[ri], a0, a1);
                unpack2(po1[ri], b0, b1);
                float o0 = qredf(a0 + a1);
                float o1 = qredf(b0 + b1);
                float4 qv = QS[R[ri]];
                o0 += st ? qv.z : qv.x;
                o1 += st ? qv.w : qv.y;
                float ls = fminf(fmaxf(o0, -5.0f), 5.0f);
                float up_new = cup[ri] * __expf(ls) + o1;
                lsum[ri] += ls;
                cup[ri] = cin[ri];
                cin[ri] = up_new;
            }
        }

        // after stage 1: cin = x_final, cup = y_final. tq==0 lanes store directly.
        if (tq == 0) {
            #pragma unroll
            for (int ri = 0; ri < 4; ri++) {
                long rr = base + R[ri];
                if (rr < M) {
                    ((float2*)out)[rr] = make_float2(cin[ri], cup[ri]);
                    out[2 * M + rr] = lsum[ri];
                }
            }
        }
    }
}

extern "C" void kernel_launch(void* const* d_in, const int* in_sizes, int n_in,
                              void* d_out, int out_size) {
    const float* coords = (const float*)d_in[0];
    const float* c      = (const float*)d_in[1];
    const float* Wx1    = (const float*)d_in[2];
    const float* bx1    = (const float*)d_in[3];
    const float* Wx2    = (const float*)d_in[4];
    const float* bx2    = (const float*)d_in[5];
    const float* Wy1    = (const float*)d_in[6];
    const float* by1    = (const float*)d_in[7];
    const float* Wy2    = (const float*)d_in[8];
    const float* by2    = (const float*)d_in[9];
    float* out = (float*)d_out;

    long M = (long)in_sizes[1] / 64;
    long rowsPerCta = 128L * TILES;
    int grid = (int)((M + rowsPerCta - 1) / rowsPerCta);

    cudaFuncSetAttribute(coupling_mma_kernel,
                         cudaFuncAttributeMaxDynamicSharedMemorySize, SMEM_BYTES);
    coupling_mma_kernel<<<grid, THREADS, SMEM_BYTES>>>(coords, c,
                                                       Wx1, bx1, Wx2, bx2,
                                                       Wy1, by1, Wy2, by2,
                                                       out, M);
}